// round 6
// baseline (speedup 1.0000x reference)
#include <cuda_runtime.h>
#include <math.h>

#define NN 50000
#define EE 1600000
#define TT 12
#define FF 16
#define HH 128
#define OUTD 3
#define HOR 6

#define AS_STRIDE 68            // k-major A stride (floats); 16B-aligned rows
#define HRS2 129                // hr row-major stride
#define SM_AS (144 * AS_STRIDE) // 9792 floats
#define SM_HRS (64 * HRS2)      // 8256 floats
#define SM_BS (2 * 16 * 128)    // 4096 floats (double-buffered B)
#define SMEM_CELL ((SM_AS + SM_HRS + SM_BS) * 4)  // 88576 B -> 2 blocks/SM

// ---------------- scratch (static device globals; no allocation) ----------------
__device__ float g_dinv_all[TT * NN];
__device__ float g_agg_all[(size_t)TT * NN * FF];
__device__ float g_aggh[2 * NN * FF];       // horizon agg ping-pong
__device__ float g_nrm11[EE];               // precomputed edge norms, graph 11
__device__ float g_h[NN * HH];
__device__ float g_hw[NN * HH];
__device__ unsigned char g_maskc[TT * NN];
__device__ unsigned char g_meff[TT * NN];
__device__ float g_Bzr_top[16 * 256];
__device__ float g_bzr[256];
__device__ float g_Bzr_bot[128 * 256];
__device__ float g_Bh_top[16 * 128];
__device__ float g_bh[128];
__device__ int g_isbyte;

// ---------------- f32x2 packed-FMA helpers ----------------
__device__ __forceinline__ unsigned long long pack2(float lo, float hi) {
    unsigned long long r;
    asm("mov.b64 %0, {%1, %2};" : "=l"(r) : "f"(lo), "f"(hi));
    return r;
}
__device__ __forceinline__ void fma2(unsigned long long& acc,
                                     unsigned long long a, unsigned long long b) {
    asm("fma.rn.f32x2 %0, %1, %2, %0;" : "+l"(acc) : "l"(a), "l"(b));
}
__device__ __forceinline__ float2 unpack2(unsigned long long v) {
    float2 f;
    asm("mov.b64 {%0, %1}, %2;" : "=f"(f.x), "=f"(f.y) : "l"(v));
    return f;
}

// ---------------- mask dtype detection + canonicalization ----------------
__global__ void k_detect(const unsigned char* raw) {
    __shared__ int cnt;
    if (threadIdx.x == 0) cnt = 0;
    __syncthreads();
    int c = 0;
    for (int i = threadIdx.x; i < 4096; i += blockDim.x)
        c += (raw[i] != 0);
    atomicAdd(&cnt, c);
    __syncthreads();
    if (threadIdx.x == 0) g_isbyte = (cnt > 2048) ? 1 : 0;
}

__global__ void k_convert(const unsigned char* raw) {
    int n = blockIdx.x * blockDim.x + threadIdx.x;
    if (n >= NN) return;
    int isb = g_isbyte;
    int seen = 0;
#pragma unroll
    for (int t = 0; t < TT; ++t) {
        int m = isb ? (raw[t * NN + n] != 0)
                    : (((const int*)raw)[t * NN + n] != 0);
        g_maskc[t * NN + n] = (unsigned char)m;
        g_meff[t * NN + n] = (unsigned char)(m & seen);
        seen |= m;
    }
}

// ---------------- weight fusion ----------------
__global__ void k_fuse(const float* __restrict__ Wcz, const float* __restrict__ Wlz,
                       const float* __restrict__ blz, const float* __restrict__ bcz,
                       const float* __restrict__ Wcr, const float* __restrict__ Wlr,
                       const float* __restrict__ blr, const float* __restrict__ bcr,
                       const float* __restrict__ Wch, const float* __restrict__ Wlh,
                       const float* __restrict__ blh, const float* __restrict__ bch) {
    int i = blockIdx.x * blockDim.x + threadIdx.x;
    if (i < 16 * 256) {                           // Bzr_top
        int k = i / 256, c = i % 256, cc = c & 127;
        const float* A = (c < 128) ? Wcz : Wcr;
        const float* B = (c < 128) ? Wlz : Wlr;
        float s = 0.f;
        for (int j = 0; j < 128; ++j) s += A[k * 128 + j] * B[j * 128 + cc];
        g_Bzr_top[i] = s;
    } else if (i < 4096 + 2048) {                 // Bh_top
        int r = i - 4096; int k = r / 128, c = r % 128;
        float s = 0.f;
        for (int j = 0; j < 128; ++j) s += Wch[k * 128 + j] * Wlh[j * 128 + c];
        g_Bh_top[r] = s;
    } else if (i < 6144 + 256) {                  // fused z|r bias
        int c = i - 6144; int cc = c & 127;
        const float* bc = (c < 128) ? bcz : bcr;
        const float* B  = (c < 128) ? Wlz : Wlr;
        const float* bl = (c < 128) ? blz : blr;
        float s = bl[cc];
        for (int j = 0; j < 128; ++j) s += bc[j] * B[j * 128 + cc];
        g_bzr[c] = s;
    } else if (i < 6400 + 128) {                  // fused h bias
        int c = i - 6400;
        float s = blh[c];
        for (int j = 0; j < 128; ++j) s += bch[j] * Wlh[j * 128 + c];
        g_bh[c] = s;
    } else if (i < 6528 + 128 * 256) {            // Bzr_bot pack
        int r = i - 6528; int k = r / 256, c = r % 256;
        g_Bzr_bot[r] = (c < 128) ? Wlz[(128 + k) * 128 + c]
                                 : Wlr[(128 + k) * 128 + (c - 128)];
    }
}

__global__ void k_init() {
    int i = blockIdx.x * blockDim.x + threadIdx.x;
    if (i < NN * HH) g_h[i] = 0.f;
    if (i < TT * NN) g_dinv_all[i] = 0.f;
}

// ---------------- degree / dinv / aggregation (batched) ----------------
__global__ void k_deg_all(const int* __restrict__ ei, const float* __restrict__ ea) {
    int e = blockIdx.x * blockDim.x + threadIdx.x;
    if (e >= TT * EE) return;
    int t = e / EE, le = e - t * EE;
    int dst = ei[(size_t)t * 2 * EE + EE + le];
    atomicAdd(&g_dinv_all[t * NN + dst], ea[(size_t)t * EE + le]);
}

__global__ void k_dinv_fin() {
    int i = blockIdx.x * blockDim.x + threadIdx.x;
    if (i < TT * NN) g_dinv_all[i] = rsqrtf(g_dinv_all[i] + 1.0f);
}

__global__ void k_aggself_all(const float* __restrict__ x_seq) {
    int i = blockIdx.x * blockDim.x + threadIdx.x;
    if (i >= TT * NN) return;
    int t = i / NN, n = i - t * NN;
    float di = g_dinv_all[i];
    float s = di * di;
    const float4* xp = (const float4*)(x_seq + (size_t)t * NN * FF + (size_t)n * FF);
    float4* op = (float4*)(g_agg_all + (size_t)t * NN * FF + (size_t)n * FF);
    float4 a = xp[0], b = xp[1], c = xp[2], d = xp[3];
    op[0] = make_float4(s * a.x, s * a.y, s * a.z, s * a.w);
    op[1] = make_float4(s * b.x, s * b.y, s * b.z, s * b.w);
    op[2] = make_float4(s * c.x, s * c.y, s * c.z, s * c.w);
    op[3] = make_float4(s * d.x, s * d.y, s * d.z, s * d.w);
}

#define REDV4(p, a, b, c, d)                                              \
    asm volatile("red.global.add.v4.f32 [%0], {%1,%2,%3,%4};"             \
                 :: "l"(p), "f"(a), "f"(b), "f"(c), "f"(d) : "memory")
#define REDV2(p, a, b)                                                    \
    asm volatile("red.global.add.v2.f32 [%0], {%1,%2};"                   \
                 :: "l"(p), "f"(a), "f"(b) : "memory")
#define RED1(p, a)                                                        \
    asm volatile("red.global.add.f32 [%0], %1;"                           \
                 :: "l"(p), "f"(a) : "memory")

__global__ void k_scatter_all(const int* __restrict__ ei, const float* __restrict__ ea,
                              const float* __restrict__ x_seq) {
    int e = blockIdx.x * blockDim.x + threadIdx.x;
    if (e >= TT * EE) return;
    int t = e / EE, le = e - t * EE;
    const int* eit = ei + (size_t)t * 2 * EE;
    int s = eit[le], d = eit[EE + le];
    const float* dinv = g_dinv_all + t * NN;
    float nrm = dinv[s] * ea[(size_t)t * EE + le] * dinv[d];
    if (t == 11) g_nrm11[le] = nrm;
    const float4* xp = (const float4*)(x_seq + (size_t)t * NN * FF + (size_t)s * FF);
    float4 a = xp[0], b = xp[1], c = xp[2], dd = xp[3];
    float* o = g_agg_all + (size_t)t * NN * FF + (size_t)d * FF;
    REDV4(o + 0,  nrm * a.x,  nrm * a.y,  nrm * a.z,  nrm * a.w);
    REDV4(o + 4,  nrm * b.x,  nrm * b.y,  nrm * b.z,  nrm * b.w);
    REDV4(o + 8,  nrm * c.x,  nrm * c.y,  nrm * c.z,  nrm * c.w);
    REDV4(o + 12, nrm * dd.x, nrm * dd.y, nrm * dd.z, nrm * dd.w);
}

// ---------------- fused TGCN cell ----------------
__device__ __forceinline__ float sigmoidf_(float v) {
    return 1.0f / (1.0f + __expf(-v));
}

__device__ __forceinline__ void ldB_zr(float* dst, int chunk, int c0, int bk, int bc) {
    const float* Bg = (chunk == 0)
        ? (g_Bzr_top + bk * 256 + c0 + bc)
        : (g_Bzr_bot + ((chunk - 1) * 16 + bk) * 256 + c0 + bc);
    *(float4*)&dst[bk * 128 + bc]     = *(const float4*)Bg;
    *(float4*)&dst[bk * 128 + bc + 4] = *(const float4*)(Bg + 4);
}
__device__ __forceinline__ void ldB_h(float* dst, int chunk,
                                      const float* __restrict__ Wlh_bot,
                                      int bk, int bc) {
    const float* Bg = (chunk == 0)
        ? (g_Bh_top + bk * 128 + bc)
        : (Wlh_bot + ((size_t)((chunk - 1) * 16 + bk)) * 128 + bc);
    *(float4*)&dst[bk * 128 + bc]     = *(const float4*)Bg;
    *(float4*)&dst[bk * 128 + bc + 4] = *(const float4*)(Bg + 4);
}

// hr column permutation (bank-spread): bijection on 0..127
__device__ __forceinline__ int cperm(int c) { return ((c & 7) << 4) | (c >> 3); }

#define GEMM_K16(RA_BLOCK, BsBuf)                                           \
    _Pragma("unroll")                                                       \
    for (int kk = 0; kk < 16; ++kk) {                                       \
        float ra[4];                                                        \
        RA_BLOCK;                                                           \
        ulonglong2 b01 = *(const ulonglong2*)&(BsBuf)[kk * 128 + tx * 8];   \
        ulonglong2 b23 = *(const ulonglong2*)&(BsBuf)[kk * 128 + tx * 8 + 4];\
        unsigned long long rb0 = b01.x, rb1 = b01.y, rb2 = b23.x, rb3 = b23.y;\
        _Pragma("unroll")                                                   \
        for (int i = 0; i < 4; ++i) {                                       \
            unsigned long long rap = pack2(ra[i], ra[i]);                   \
            fma2(accp[i][0], rap, rb0);                                     \
            fma2(accp[i][1], rap, rb1);                                     \
            fma2(accp[i][2], rap, rb2);                                     \
            fma2(accp[i][3], rap, rb3);                                     \
        }                                                                   \
    }

#define RA_AGG                                                              \
    { float4 a4 = *(const float4*)&As[kk * AS_STRIDE + ty * 4];             \
      ra[0] = a4.x; ra[1] = a4.y; ra[2] = a4.z; ra[3] = a4.w; }
#define RA_AH                                                               \
    { int k = (chunk - 1) * 16 + kk;                                        \
      float4 a4 = *(const float4*)&As[(16 + k) * AS_STRIDE +                \
                                      ((ty ^ ((k >> 3) & 15)) << 2)];       \
      ra[0] = a4.x; ra[1] = a4.y; ra[2] = a4.z; ra[3] = a4.w; }
#define RA_HR                                                               \
    { int k = (chunk - 1) * 16 + kk; int cpk = cperm(k);                    \
      ra[0] = hrs[(ty * 4 + 0) * HRS2 + cpk];                               \
      ra[1] = hrs[(ty * 4 + 1) * HRS2 + cpk];                               \
      ra[2] = hrs[(ty * 4 + 2) * HRS2 + cpk];                               \
      ra[3] = hrs[(ty * 4 + 3) * HRS2 + cpk]; }

#define ACC_RESET()                                                         \
    _Pragma("unroll") for (int i = 0; i < 4; ++i)                           \
    _Pragma("unroll") for (int j = 0; j < 4; ++j) accp[i][j] = 0ull;

// flags: bit0 = horizon mode, bit1 = also write g_hw = mk ? hn : 0 (t==11)
__global__ __launch_bounds__(256, 2) void k_cell(const float* __restrict__ agg,
                                                 int t, int flags,
                                                 const float* __restrict__ Wlh_bot,
                                                 const float* __restrict__ headW,
                                                 const float* __restrict__ headb,
                                                 float* __restrict__ outk,
                                                 float* __restrict__ agghN) {
    extern __shared__ __align__(16) float sm[];
    float* As  = sm;                 // [144][AS_STRIDE] k-major, h-part XOR-swizzled
    float* hrs = As + SM_AS;         // [64][HRS2] hr row-major (cperm cols)
    float* Bs  = hrs + SM_HRS;       // [2][16][128]

    const int tid = threadIdx.x;
    const int n0 = blockIdx.x * 64;
    const bool horizon = (flags & 1) != 0;
    const bool wrHw = (flags & 2) != 0;
    const float* hsrc = horizon ? g_hw : g_h;
    const unsigned char* me = g_meff + (size_t)t * NN;
    const unsigned char* mk = g_maskc + (size_t)t * NN;

    const int ty = tid >> 4, tx = tid & 15;
    const int bk = tid >> 4, bc = (tid & 15) * 8;

    // ---- staging: A = [agg(16) | h_eff(128)] k-major ----
    {
        int lr = tid & 63, lg = tid >> 6;
        int nA = n0 + lr;
        bool rowValid = (nA < NN);
        bool rowOn = rowValid && (horizon || (me[nA] != 0));
        ldB_zr(Bs, 0, 0, bk, bc);
        {
            float4 v = make_float4(0.f, 0.f, 0.f, 0.f);
            if (rowValid) v = *(const float4*)(agg + (size_t)nA * 16 + 4 * lg);
            As[(4 * lg + 0) * AS_STRIDE + lr] = v.x;
            As[(4 * lg + 1) * AS_STRIDE + lr] = v.y;
            As[(4 * lg + 2) * AS_STRIDE + lr] = v.z;
            As[(4 * lg + 3) * AS_STRIDE + lr] = v.w;
        }
#pragma unroll
        for (int g = 0; g < 8; ++g) {
            int k0 = 4 * lg + 16 * g;
            float4 v = make_float4(0.f, 0.f, 0.f, 0.f);
            if (rowOn) v = *(const float4*)(hsrc + (size_t)nA * HH + k0);
            float vv[4] = {v.x, v.y, v.z, v.w};
#pragma unroll
            for (int j = 0; j < 4; ++j) {
                int k = k0 + j;
                As[(16 + k) * AS_STRIDE + (((lr >> 2) ^ ((k >> 3) & 15)) << 2) +
                   (lr & 3)] = vv[j];
            }
        }
    }
    __syncthreads();

    unsigned long long accp[4][4];
    float zreg[4][8];

    // ================= phase Z =================
    ACC_RESET();
    for (int chunk = 0; chunk < 9; ++chunk) {
        float* cur = Bs + (chunk & 1) * 2048;
        if (chunk < 8) ldB_zr(Bs + ((chunk + 1) & 1) * 2048, chunk + 1, 0, bk, bc);
        if (chunk == 0) { GEMM_K16(RA_AGG, cur); }
        else           { GEMM_K16(RA_AH, cur); }
        __syncthreads();
    }
#pragma unroll
    for (int i = 0; i < 4; ++i)
#pragma unroll
        for (int jp = 0; jp < 4; ++jp) {
            float2 v = unpack2(accp[i][jp]);
            int c = tx * 8 + 2 * jp;
            zreg[i][2 * jp]     = sigmoidf_(v.x + g_bzr[c]);
            zreg[i][2 * jp + 1] = sigmoidf_(v.y + g_bzr[c + 1]);
        }

    // ================= phase R =================
    ACC_RESET();
    ldB_zr(Bs, 0, 128, bk, bc);
    __syncthreads();
    for (int chunk = 0; chunk < 9; ++chunk) {
        float* cur = Bs + (chunk & 1) * 2048;
        if (chunk < 8) ldB_zr(Bs + ((chunk + 1) & 1) * 2048, chunk + 1, 128, bk, bc);
        if (chunk == 0) { GEMM_K16(RA_AGG, cur); }
        else           { GEMM_K16(RA_AH, cur); }
        __syncthreads();
    }
    // hr = heff * r  (row-major, cperm columns)
#pragma unroll
    for (int i = 0; i < 4; ++i) {
        int ml = ty * 4 + i;
#pragma unroll
        for (int jp = 0; jp < 4; ++jp) {
            float2 v = unpack2(accp[i][jp]);
#pragma unroll
            for (int u = 0; u < 2; ++u) {
                int c = tx * 8 + 2 * jp + u;
                float r = sigmoidf_(((u == 0) ? v.x : v.y) + g_bzr[128 + c]);
                float heff = As[(16 + c) * AS_STRIDE +
                                ((ty ^ ((c >> 3) & 15)) << 2) + i];
                hrs[ml * HRS2 + cperm(c)] = heff * r;
            }
        }
    }
    __syncthreads();

    // ================= phase H =================
    ACC_RESET();
    ldB_h(Bs, 0, Wlh_bot, bk, bc);
    __syncthreads();
    for (int chunk = 0; chunk < 9; ++chunk) {
        float* cur = Bs + (chunk & 1) * 2048;
        if (chunk < 8) ldB_h(Bs + ((chunk + 1) & 1) * 2048, chunk + 1, Wlh_bot, bk, bc);
        if (chunk == 0) { GEMM_K16(RA_AGG, cur); }
        else           { GEMM_K16(RA_HR, cur); }
        __syncthreads();
    }

    // ================= combine =================
#pragma unroll
    for (int i = 0; i < 4; ++i) {
        int ml = ty * 4 + i;
        int n = n0 + ml;
        if (n >= NN) continue;
        bool wr = horizon ? true : (mk[n] != 0);
#pragma unroll
        for (int jp = 0; jp < 4; ++jp) {
            float2 v = unpack2(accp[i][jp]);
#pragma unroll
            for (int u = 0; u < 2; ++u) {
                int c = tx * 8 + 2 * jp + u;
                float ht = tanhf(((u == 0) ? v.x : v.y) + g_bh[c]);
                float z = zreg[i][2 * jp + u];
                float heff = As[(16 + c) * AS_STRIDE +
                                ((ty ^ ((c >> 3) & 15)) << 2) + i];
                float hn = z * heff + (1.f - z) * ht;
                if (horizon) {
                    g_hw[(size_t)n * HH + c] = hn;
                    hrs[ml * HRS2 + c] = hn;   // plain layout for pred
                } else {
                    if (wr) g_h[(size_t)n * HH + c] = hn;
                    if (wrHw) g_hw[(size_t)n * HH + c] = wr ? hn : 0.f;
                }
            }
        }
    }

    // ================= fused head prediction (horizon only) =================
    if (horizon) {
        if (tid < 96) {
            float4 w = *(const float4*)(headW + tid * 4);
            As[tid * 4 + 0] = w.x; As[tid * 4 + 1] = w.y;
            As[tid * 4 + 2] = w.z; As[tid * 4 + 3] = w.w;
        }
        __syncthreads();
        if (tid < 64) {
            int n = n0 + tid;
            if (n < NN) {
                float p0 = 0.f, p1 = 0.f, p2 = 0.f;
#pragma unroll 8
                for (int c = 0; c < 128; ++c) {
                    float hv = hrs[tid * HRS2 + c];
                    p0 += hv * As[c * 3 + 0];
                    p1 += hv * As[c * 3 + 1];
                    p2 += hv * As[c * 3 + 2];
                }
                p0 += headb[0]; p1 += headb[1]; p2 += headb[2];
                outk[n * 3 + 0] = p0;
                outk[n * 3 + 1] = p1;
                outk[n * 3 + 2] = p2;
                float di = g_dinv_all[11 * NN + n];
                float s = di * di;
                agghN[n * FF + 0] = s * p0;   // self-term for next horizon step
                agghN[n * FF + 1] = s * p1;
                agghN[n * FF + 2] = s * p2;
            }
        }
    }
}

// ---------------- transition / horizon helpers ----------------
__global__ void k_transition(const float* __restrict__ agg11) {
    int i = blockIdx.x * blockDim.x + threadIdx.x;
    if (i >= NN * FF) return;
    float v = agg11[i];
    g_aggh[i] = v;
    g_aggh[NN * FF + i] = v;
}

__global__ void k_scatter3(const int* __restrict__ ei11,
                           const float* __restrict__ pred,
                           float* __restrict__ target) {
    int e = blockIdx.x * blockDim.x + threadIdx.x;
    if (e >= EE) return;
    int s = ei11[e], d = ei11[EE + e];
    float nrm = g_nrm11[e];
    float p0 = pred[s * 3 + 0], p1 = pred[s * 3 + 1], p2 = pred[s * 3 + 2];
    float* o = target + (size_t)d * FF;
    REDV2(o, nrm * p0, nrm * p1);
    RED1(o + 2, nrm * p2);
}

// ---------------- launch ----------------
extern "C" void kernel_launch(void* const* d_in, const int* in_sizes, int n_in,
                              void* d_out, int out_size) {
    const float* x_seq = (const float*)d_in[0];
    const int*   ei    = (const int*)d_in[1];
    const float* ea    = (const float*)d_in[2];
    const unsigned char* mraw = (const unsigned char*)d_in[3];
    const float* Wcz = (const float*)d_in[4];
    const float* bcz = (const float*)d_in[5];
    const float* Wlz = (const float*)d_in[6];
    const float* blz = (const float*)d_in[7];
    const float* Wcr = (const float*)d_in[8];
    const float* bcr = (const float*)d_in[9];
    const float* Wlr = (const float*)d_in[10];
    const float* blr = (const float*)d_in[11];
    const float* Wch = (const float*)d_in[12];
    const float* bch = (const float*)d_in[13];
    const float* Wlh = (const float*)d_in[14];
    const float* blh = (const float*)d_in[15];
    const float* hW  = (const float*)d_in[16];
    const float* hb  = (const float*)d_in[17];
    float* out = (float*)d_out;

    void* p;
    cudaGetSymbolAddress(&p, g_agg_all);
    const float* agg_all = (const float*)p;
    cudaGetSymbolAddress(&p, g_aggh);
    float* aggh = (float*)p;

    static int s_attr_done = 0;
    if (!s_attr_done) {
        cudaFuncSetAttribute(k_cell, cudaFuncAttributeMaxDynamicSharedMemorySize,
                             SMEM_CELL);
        s_attr_done = 1;
    }

    const int THR = 256;

    k_detect<<<1, THR>>>(mraw);
    k_convert<<<(NN + THR - 1) / THR, THR>>>(mraw);
    k_fuse<<<(6528 + 128 * 256 + THR - 1) / THR, THR>>>(Wcz, Wlz, blz, bcz,
                                                        Wcr, Wlr, blr, bcr,
                                                        Wch, Wlh, blh, bch);
    k_init<<<(NN * HH + THR - 1) / THR, THR>>>();
    k_deg_all<<<(TT * EE + THR - 1) / THR, THR>>>(ei, ea);
    k_dinv_fin<<<(TT * NN + THR - 1) / THR, THR>>>();
    k_aggself_all<<<(TT * NN + THR - 1) / THR, THR>>>(x_seq);
    k_scatter_all<<<(TT * EE + THR - 1) / THR, THR>>>(ei, ea, x_seq);

    dim3 gC((NN + 63) / 64);
    const float* Wlh_bot = Wlh + 128 * 128;

    for (int t = 0; t < TT; ++t) {
        const float* aggt = agg_all + (size_t)t * NN * FF;
        int flags = (t == 11) ? 2 : 0;
        k_cell<<<gC, THR, SMEM_CELL>>>(aggt, t, flags, Wlh_bot,
                                       hW, hb, nullptr, nullptr);
    }

    const float* agg11 = agg_all + (size_t)11 * NN * FF;
    k_transition<<<(NN * FF + THR - 1) / THR, THR>>>(agg11);

    const int* eiL = ei + (size_t)11 * 2 * EE;

    for (int k = 0; k < HOR; ++k) {
        const float* aggk = (k == 0) ? agg11 : (aggh + (size_t)(k & 1) * NN * FF);
        float* agghN = aggh + (size_t)((k + 1) & 1) * NN * FF;
        if (k > 0) {
            const float* predPrev = out + (size_t)(k - 1) * NN * OUTD;
            k_scatter3<<<(EE + THR - 1) / THR, THR>>>(
                eiL, predPrev, aggh + (size_t)(k & 1) * NN * FF);
        }
        k_cell<<<gC, THR, SMEM_CELL>>>(aggk, 11, 1, Wlh_bot, hW, hb,
                                       out + (size_t)k * NN * OUTD, agghN);
    }
}

// round 7
// speedup vs baseline: 1.1429x; 1.1429x over previous
#include <cuda_runtime.h>
#include <math.h>

#define NN 50000
#define EE 1600000
#define TT 12
#define FF 16
#define HH 128
#define OUTD 3
#define HOR 6

#define SM_AS (144 * 128)      // A = [agg|h] k-major, h-part XOR-swizzled
#define SM_HRS (128 * 129)     // hr k-major swizzled; later ht/hn row-major s129
#define SM_BS (2 * 16 * 128)   // double-buffered B
#define SMEM_CELL ((SM_AS + SM_HRS + SM_BS) * 4)   // 156160 B

// ---------------- scratch (static device globals; no allocation) ----------------
__device__ float g_dinv_all[TT * NN];
__device__ float g_agg_all[(size_t)TT * NN * FF];
__device__ float g_aggh[2 * NN * FF];       // horizon agg ping-pong
__device__ float g_nrm11[EE];
__device__ float g_h[NN * HH];
__device__ float g_hw[NN * HH];
__device__ unsigned char g_maskc[TT * NN];
__device__ unsigned char g_meff[TT * NN];
__device__ float g_Bzr_top[16 * 256];
__device__ float g_bzr[256];
__device__ float g_Bzr_bot[128 * 256];
__device__ float g_Bh_top[16 * 128];
__device__ float g_bh[128];
__device__ int g_isbyte;

// ---------------- f32x2 packed-FMA helpers ----------------
__device__ __forceinline__ unsigned long long pack2(float lo, float hi) {
    unsigned long long r;
    asm("mov.b64 %0, {%1, %2};" : "=l"(r) : "f"(lo), "f"(hi));
    return r;
}
__device__ __forceinline__ void fma2(unsigned long long& acc,
                                     unsigned long long a, unsigned long long b) {
    asm("fma.rn.f32x2 %0, %1, %2, %0;" : "+l"(acc) : "l"(a), "l"(b));
}
__device__ __forceinline__ float2 unpack2(unsigned long long v) {
    float2 f;
    asm("mov.b64 {%0, %1}, %2;" : "=f"(f.x), "=f"(f.y) : "l"(v));
    return f;
}

// ---------------- mask dtype detection + canonicalization ----------------
__global__ void k_detect(const unsigned char* raw) {
    __shared__ int cnt;
    if (threadIdx.x == 0) cnt = 0;
    __syncthreads();
    int c = 0;
    for (int i = threadIdx.x; i < 4096; i += blockDim.x)
        c += (raw[i] != 0);
    atomicAdd(&cnt, c);
    __syncthreads();
    if (threadIdx.x == 0) g_isbyte = (cnt > 2048) ? 1 : 0;
}

__global__ void k_convert(const unsigned char* raw) {
    int n = blockIdx.x * blockDim.x + threadIdx.x;
    if (n >= NN) return;
    int isb = g_isbyte;
    int seen = 0;
#pragma unroll
    for (int t = 0; t < TT; ++t) {
        int m = isb ? (raw[t * NN + n] != 0)
                    : (((const int*)raw)[t * NN + n] != 0);
        g_maskc[t * NN + n] = (unsigned char)m;
        g_meff[t * NN + n] = (unsigned char)(m & seen);
        seen |= m;
    }
}

// ---------------- weight fusion ----------------
__global__ void k_fuse(const float* __restrict__ Wcz, const float* __restrict__ Wlz,
                       const float* __restrict__ blz, const float* __restrict__ bcz,
                       const float* __restrict__ Wcr, const float* __restrict__ Wlr,
                       const float* __restrict__ blr, const float* __restrict__ bcr,
                       const float* __restrict__ Wch, const float* __restrict__ Wlh,
                       const float* __restrict__ blh, const float* __restrict__ bch) {
    int i = blockIdx.x * blockDim.x + threadIdx.x;
    if (i < 16 * 256) {
        int k = i / 256, c = i % 256, cc = c & 127;
        const float* A = (c < 128) ? Wcz : Wcr;
        const float* B = (c < 128) ? Wlz : Wlr;
        float s = 0.f;
        for (int j = 0; j < 128; ++j) s += A[k * 128 + j] * B[j * 128 + cc];
        g_Bzr_top[i] = s;
    } else if (i < 4096 + 2048) {
        int r = i - 4096; int k = r / 128, c = r % 128;
        float s = 0.f;
        for (int j = 0; j < 128; ++j) s += Wch[k * 128 + j] * Wlh[j * 128 + c];
        g_Bh_top[r] = s;
    } else if (i < 6144 + 256) {
        int c = i - 6144; int cc = c & 127;
        const float* bc = (c < 128) ? bcz : bcr;
        const float* B  = (c < 128) ? Wlz : Wlr;
        const float* bl = (c < 128) ? blz : blr;
        float s = bl[cc];
        for (int j = 0; j < 128; ++j) s += bc[j] * B[j * 128 + cc];
        g_bzr[c] = s;
    } else if (i < 6400 + 128) {
        int c = i - 6400;
        float s = blh[c];
        for (int j = 0; j < 128; ++j) s += bch[j] * Wlh[j * 128 + c];
        g_bh[c] = s;
    } else if (i < 6528 + 128 * 256) {
        int r = i - 6528; int k = r / 256, c = r % 256;
        g_Bzr_bot[r] = (c < 128) ? Wlz[(128 + k) * 128 + c]
                                 : Wlr[(128 + k) * 128 + (c - 128)];
    }
}

__global__ void k_init() {
    int i = blockIdx.x * blockDim.x + threadIdx.x;
    if (i < NN * HH) g_h[i] = 0.f;
    if (i < TT * NN) g_dinv_all[i] = 0.f;
}

// ---------------- degree / dinv / aggregation (batched) ----------------
__global__ void k_deg_all(const int* __restrict__ ei, const float* __restrict__ ea) {
    int e = blockIdx.x * blockDim.x + threadIdx.x;
    if (e >= TT * EE) return;
    int t = e / EE, le = e - t * EE;
    int dst = ei[(size_t)t * 2 * EE + EE + le];
    atomicAdd(&g_dinv_all[t * NN + dst], ea[(size_t)t * EE + le]);
}

__global__ void k_dinv_fin() {
    int i = blockIdx.x * blockDim.x + threadIdx.x;
    if (i < TT * NN) g_dinv_all[i] = rsqrtf(g_dinv_all[i] + 1.0f);
}

__global__ void k_aggself_all(const float* __restrict__ x_seq) {
    int i = blockIdx.x * blockDim.x + threadIdx.x;
    if (i >= TT * NN) return;
    int t = i / NN, n = i - t * NN;
    float di = g_dinv_all[i];
    float s = di * di;
    const float4* xp = (const float4*)(x_seq + (size_t)t * NN * FF + (size_t)n * FF);
    float4* op = (float4*)(g_agg_all + (size_t)t * NN * FF + (size_t)n * FF);
    float4 a = xp[0], b = xp[1], c = xp[2], d = xp[3];
    op[0] = make_float4(s * a.x, s * a.y, s * a.z, s * a.w);
    op[1] = make_float4(s * b.x, s * b.y, s * b.z, s * b.w);
    op[2] = make_float4(s * c.x, s * c.y, s * c.z, s * c.w);
    op[3] = make_float4(s * d.x, s * d.y, s * d.z, s * d.w);
}

#define REDV4(p, a, b, c, d)                                              \
    asm volatile("red.global.add.v4.f32 [%0], {%1,%2,%3,%4};"             \
                 :: "l"(p), "f"(a), "f"(b), "f"(c), "f"(d) : "memory")
#define REDV2(p, a, b)                                                    \
    asm volatile("red.global.add.v2.f32 [%0], {%1,%2};"                   \
                 :: "l"(p), "f"(a), "f"(b) : "memory")
#define RED1(p, a)                                                        \
    asm volatile("red.global.add.f32 [%0], %1;"                           \
                 :: "l"(p), "f"(a) : "memory")

__global__ void k_scatter_all(const int* __restrict__ ei, const float* __restrict__ ea,
                              const float* __restrict__ x_seq) {
    int e = blockIdx.x * blockDim.x + threadIdx.x;
    if (e >= TT * EE) return;
    int t = e / EE, le = e - t * EE;
    const int* eit = ei + (size_t)t * 2 * EE;
    int s = eit[le], d = eit[EE + le];
    const float* dinv = g_dinv_all + t * NN;
    float nrm = dinv[s] * ea[(size_t)t * EE + le] * dinv[d];
    if (t == 11) g_nrm11[le] = nrm;
    const float4* xp = (const float4*)(x_seq + (size_t)t * NN * FF + (size_t)s * FF);
    float4 a = xp[0], b = xp[1], c = xp[2], dd = xp[3];
    float* o = g_agg_all + (size_t)t * NN * FF + (size_t)d * FF;
    REDV4(o + 0,  nrm * a.x,  nrm * a.y,  nrm * a.z,  nrm * a.w);
    REDV4(o + 4,  nrm * b.x,  nrm * b.y,  nrm * b.z,  nrm * b.w);
    REDV4(o + 8,  nrm * c.x,  nrm * c.y,  nrm * c.z,  nrm * c.w);
    REDV4(o + 12, nrm * dd.x, nrm * dd.y, nrm * dd.z, nrm * dd.w);
}

// ---------------- fused TGCN cell ----------------
__device__ __forceinline__ float sigmoidf_(float v) {
    return 1.0f / (1.0f + __expf(-v));
}

__device__ __forceinline__ void ldB_zr(float* dst, int chunk, int c0, int bk, int bc) {
    const float* Bg = (chunk == 0)
        ? (g_Bzr_top + bk * 256 + c0 + bc)
        : (g_Bzr_bot + ((chunk - 1) * 16 + bk) * 256 + c0 + bc);
    *(float4*)&dst[bk * 128 + bc]     = *(const float4*)Bg;
    *(float4*)&dst[bk * 128 + bc + 4] = *(const float4*)(Bg + 4);
}
__device__ __forceinline__ void ldB_h(float* dst, int chunk,
                                      const float* __restrict__ Wlh_bot,
                                      int bk, int bc) {
    const float* Bg = (chunk == 0)
        ? (g_Bh_top + bk * 128 + bc)
        : (Wlh_bot + ((size_t)((chunk - 1) * 16 + bk)) * 128 + bc);
    *(float4*)&dst[bk * 128 + bc]     = *(const float4*)Bg;
    *(float4*)&dst[bk * 128 + bc + 4] = *(const float4*)(Bg + 4);
}

// swizzled scalar index for As-h / hrs-k layouts: row*128 + ((ml/4 ^ g)<<2)+(ml&3)
__device__ __forceinline__ int swidx(int row, int ml, int g) {
    return row * 128 + ((((ml >> 2) ^ g) << 2)) + (ml & 3);
}
// ht/hn column permutation: bijection on 0..127, conflict-free both ways
__device__ __forceinline__ int cperm(int c) { return ((c & 7) << 4) | (c >> 3); }

#define GEMM_K16(RA_BLOCK, BsBuf)                                           \
    _Pragma("unroll")                                                       \
    for (int kk = 0; kk < 16; ++kk) {                                       \
        float ra[8];                                                        \
        RA_BLOCK;                                                           \
        ulonglong2 b01 = *(const ulonglong2*)&(BsBuf)[kk * 128 + tx * 8];   \
        ulonglong2 b23 = *(const ulonglong2*)&(BsBuf)[kk * 128 + tx * 8 + 4];\
        unsigned long long rb0 = b01.x, rb1 = b01.y, rb2 = b23.x, rb3 = b23.y;\
        _Pragma("unroll")                                                   \
        for (int i = 0; i < 8; ++i) {                                       \
            unsigned long long rap = pack2(ra[i], ra[i]);                   \
            fma2(accp[i][0], rap, rb0);                                     \
            fma2(accp[i][1], rap, rb1);                                     \
            fma2(accp[i][2], rap, rb2);                                     \
            fma2(accp[i][3], rap, rb3);                                     \
        }                                                                   \
    }

#define RA_AGG                                                              \
    { *(float4*)ra       = *(const float4*)&As[kk * 128 + ty * 8];          \
      *(float4*)(ra + 4) = *(const float4*)&As[kk * 128 + ty * 8 + 4]; }
#define RA_AH                                                               \
    { int k = (chunk - 1) * 16 + kk; int g = (k >> 3) & 15;                 \
      *(float4*)ra       = *(const float4*)&As[(16 + k) * 128 +             \
                                               (((2 * ty) ^ g) << 2)];      \
      *(float4*)(ra + 4) = *(const float4*)&As[(16 + k) * 128 +             \
                                               (((2 * ty + 1) ^ g) << 2)]; }
#define RA_HR                                                               \
    { int k = (chunk - 1) * 16 + kk; int g = (k >> 3) & 15;                 \
      *(float4*)ra       = *(const float4*)&hrs[k * 128 +                   \
                                               (((2 * ty) ^ g) << 2)];      \
      *(float4*)(ra + 4) = *(const float4*)&hrs[k * 128 +                   \
                                               (((2 * ty + 1) ^ g) << 2)]; }

#define ACC_RESET()                                                         \
    _Pragma("unroll") for (int i = 0; i < 8; ++i)                           \
    _Pragma("unroll") for (int j = 0; j < 4; ++j) accp[i][j] = 0ull;

// flags: bit0 = horizon mode, bit1 = also write g_hw = mk ? hn : 0 (t==11)
__global__ __launch_bounds__(256) void k_cell(const float* __restrict__ agg,
                                              int t, int flags,
                                              const float* __restrict__ Wlh_bot,
                                              const float* __restrict__ headW,
                                              const float* __restrict__ headb,
                                              float* __restrict__ outk,
                                              float* __restrict__ agghN) {
    extern __shared__ __align__(16) float sm[];
    float* As  = sm;                 // [144][128]; h-part XOR-swizzled
    float* hrs = As + SM_AS;         // hr k-major swizzled; then ht/hn @ stride 129
    float* Bs  = hrs + SM_HRS;       // [2][16][128]

    const int tid = threadIdx.x;
    const int n0 = blockIdx.x * 128;
    const bool horizon = (flags & 1) != 0;
    const bool wrHw = (flags & 2) != 0;
    const float* hsrc = horizon ? g_hw : g_h;
    const unsigned char* me = g_meff + (size_t)t * NN;
    const unsigned char* mk = g_maskc + (size_t)t * NN;

    const int ty = tid >> 4, tx = tid & 15;
    const int bk = tid >> 4, bc = (tid & 15) * 8;

    // ---- staging: A = [agg(16) | h_eff(128)] k-major; prefetch B for phase R ----
    ldB_zr(Bs, 0, 128, bk, bc);
    {
        int lr = tid >> 1, lq = tid & 1;
        int nA = n0 + lr;
        bool rowValid = (nA < NN);
        bool rowOn = rowValid && (horizon || (me[nA] != 0));
#pragma unroll
        for (int h2 = 0; h2 < 2; ++h2) {
            int kq = lq + 2 * h2;
            float4 v = make_float4(0.f, 0.f, 0.f, 0.f);
            if (rowValid) v = *(const float4*)(agg + (size_t)nA * 16 + 4 * kq);
            As[(4 * kq + 0) * 128 + lr] = v.x;
            As[(4 * kq + 1) * 128 + lr] = v.y;
            As[(4 * kq + 2) * 128 + lr] = v.z;
            As[(4 * kq + 3) * 128 + lr] = v.w;
        }
#pragma unroll
        for (int g8 = 0; g8 < 8; ++g8) {
#pragma unroll
            for (int h2 = 0; h2 < 2; ++h2) {
                int k0 = 4 * (lq + 2 * h2) + 16 * g8;
                float4 v = make_float4(0.f, 0.f, 0.f, 0.f);
                if (rowOn) v = *(const float4*)(hsrc + (size_t)nA * HH + k0);
                float vv[4] = {v.x, v.y, v.z, v.w};
#pragma unroll
                for (int j = 0; j < 4; ++j) {
                    int k = k0 + j;
                    As[16 * 128 + swidx(k, lr, (k >> 3) & 15)] = vv[j];
                }
            }
        }
    }
    __syncthreads();

    unsigned long long accp[8][4];

    // ================= phase R (c0=128) =================
    ACC_RESET();
    for (int chunk = 0; chunk < 9; ++chunk) {
        float* cur = Bs + (chunk & 1) * 2048;
        if (chunk < 8) ldB_zr(Bs + ((chunk + 1) & 1) * 2048, chunk + 1, 128, bk, bc);
        if (chunk == 0) { GEMM_K16(RA_AGG, cur); }
        else            { GEMM_K16(RA_AH, cur); }
        __syncthreads();
    }
    // epilogue: hr = heff * r, k-major swizzled; prefetch B for phase H
#pragma unroll
    for (int i = 0; i < 8; ++i) {
        int ml = ty * 8 + i;
#pragma unroll
        for (int jp = 0; jp < 4; ++jp) {
            float2 v = unpack2(accp[i][jp]);
#pragma unroll
            for (int u = 0; u < 2; ++u) {
                int c = tx * 8 + 2 * jp + u;
                float r = sigmoidf_(((u == 0) ? v.x : v.y) + g_bzr[128 + c]);
                float heff = As[16 * 128 + swidx(c, ml, (c >> 3) & 15)];
                hrs[swidx(c, ml, (c >> 3) & 15)] = heff * r;
            }
        }
    }
    ldB_h(Bs, 0, Wlh_bot, bk, bc);
    __syncthreads();

    // ================= phase H~ =================
    ACC_RESET();
    for (int chunk = 0; chunk < 9; ++chunk) {
        float* cur = Bs + (chunk & 1) * 2048;
        if (chunk < 8) ldB_h(Bs + ((chunk + 1) & 1) * 2048, chunk + 1, Wlh_bot, bk, bc);
        if (chunk == 0) { GEMM_K16(RA_AGG, cur); }
        else            { GEMM_K16(RA_HR, cur); }
        __syncthreads();
    }
    // epilogue: ht = tanh(acc + bh) -> hrs row-major stride 129 (cperm cols)
#pragma unroll
    for (int i = 0; i < 8; ++i) {
        int ml = ty * 8 + i;
#pragma unroll
        for (int jp = 0; jp < 4; ++jp) {
            float2 v = unpack2(accp[i][jp]);
#pragma unroll
            for (int u = 0; u < 2; ++u) {
                int c = tx * 8 + 2 * jp + u;
                hrs[ml * 129 + cperm(c)] = tanhf(((u == 0) ? v.x : v.y) + g_bh[c]);
            }
        }
    }
    ldB_zr(Bs, 0, 0, bk, bc);
    __syncthreads();

    // ================= phase Z (c0=0) =================
    ACC_RESET();
    for (int chunk = 0; chunk < 9; ++chunk) {
        float* cur = Bs + (chunk & 1) * 2048;
        if (chunk < 8) ldB_zr(Bs + ((chunk + 1) & 1) * 2048, chunk + 1, 0, bk, bc);
        if (chunk == 0) { GEMM_K16(RA_AGG, cur); }
        else            { GEMM_K16(RA_AH, cur); }
        __syncthreads();
    }

    // ================= combine =================
#pragma unroll
    for (int i = 0; i < 8; ++i) {
        int ml = ty * 8 + i;
        int n = n0 + ml;
        bool inb = (n < NN);
        bool wr = inb && (horizon ? true : (mk[n] != 0));
#pragma unroll
        for (int jp = 0; jp < 4; ++jp) {
            float2 v = unpack2(accp[i][jp]);
#pragma unroll
            for (int u = 0; u < 2; ++u) {
                int c = tx * 8 + 2 * jp + u;
                float z = sigmoidf_(((u == 0) ? v.x : v.y) + g_bzr[c]);
                float ht = hrs[ml * 129 + cperm(c)];
                float heff = As[16 * 128 + swidx(c, ml, (c >> 3) & 15)];
                float hn = z * heff + (1.f - z) * ht;
                if (horizon) {
                    if (inb) g_hw[(size_t)n * HH + c] = hn;
                    hrs[ml * 129 + cperm(c)] = hn;  // feeds head pred
                } else {
                    if (wr) g_h[(size_t)n * HH + c] = hn;
                    if (wrHw && inb) g_hw[(size_t)n * HH + c] = wr ? hn : 0.f;
                }
            }
        }
    }

    // ================= fused head prediction (horizon only) =================
    if (horizon) {
        __syncthreads();                 // combine reads of As done before reuse
        if (tid < 96) {
            float4 w = *(const float4*)(headW + tid * 4);
            As[tid * 4 + 0] = w.x; As[tid * 4 + 1] = w.y;
            As[tid * 4 + 2] = w.z; As[tid * 4 + 3] = w.w;
        }
        __syncthreads();
        if (tid < 128) {
            int n = n0 + tid;
            if (n < NN) {
                float p0 = 0.f, p1 = 0.f, p2 = 0.f;
#pragma unroll 8
                for (int c = 0; c < 128; ++c) {
                    float hv = hrs[tid * 129 + cperm(c)];
                    p0 += hv * As[c * 3 + 0];
                    p1 += hv * As[c * 3 + 1];
                    p2 += hv * As[c * 3 + 2];
                }
                p0 += headb[0]; p1 += headb[1]; p2 += headb[2];
                outk[n * 3 + 0] = p0;
                outk[n * 3 + 1] = p1;
                outk[n * 3 + 2] = p2;
                float di = g_dinv_all[11 * NN + n];
                float s = di * di;
                agghN[n * FF + 0] = s * p0;
                agghN[n * FF + 1] = s * p1;
                agghN[n * FF + 2] = s * p2;
            }
        }
    }
}

// ---------------- transition / horizon helpers ----------------
__global__ void k_transition(const float* __restrict__ agg11) {
    int i = blockIdx.x * blockDim.x + threadIdx.x;
    if (i >= NN * FF) return;
    float v = agg11[i];
    g_aggh[i] = v;
    g_aggh[NN * FF + i] = v;
}

__global__ void k_scatter3(const int* __restrict__ ei11,
                           const float* __restrict__ pred,
                           float* __restrict__ target) {
    int e = blockIdx.x * blockDim.x + threadIdx.x;
    if (e >= EE) return;
    int s = ei11[e], d = ei11[EE + e];
    float nrm = g_nrm11[e];
    float p0 = pred[s * 3 + 0], p1 = pred[s * 3 + 1], p2 = pred[s * 3 + 2];
    float* o = target + (size_t)d * FF;
    REDV2(o, nrm * p0, nrm * p1);
    RED1(o + 2, nrm * p2);
}

// ---------------- launch ----------------
extern "C" void kernel_launch(void* const* d_in, const int* in_sizes, int n_in,
                              void* d_out, int out_size) {
    const float* x_seq = (const float*)d_in[0];
    const int*   ei    = (const int*)d_in[1];
    const float* ea    = (const float*)d_in[2];
    const unsigned char* mraw = (const unsigned char*)d_in[3];
    const float* Wcz = (const float*)d_in[4];
    const float* bcz = (const float*)d_in[5];
    const float* Wlz = (const float*)d_in[6];
    const float* blz = (const float*)d_in[7];
    const float* Wcr = (const float*)d_in[8];
    const float* bcr = (const float*)d_in[9];
    const float* Wlr = (const float*)d_in[10];
    const float* blr = (const float*)d_in[11];
    const float* Wch = (const float*)d_in[12];
    const float* bch = (const float*)d_in[13];
    const float* Wlh = (const float*)d_in[14];
    const float* blh = (const float*)d_in[15];
    const float* hW  = (const float*)d_in[16];
    const float* hb  = (const float*)d_in[17];
    float* out = (float*)d_out;

    void* p;
    cudaGetSymbolAddress(&p, g_agg_all);
    const float* agg_all = (const float*)p;
    cudaGetSymbolAddress(&p, g_aggh);
    float* aggh = (float*)p;

    static int s_attr_done = 0;
    if (!s_attr_done) {
        cudaFuncSetAttribute(k_cell, cudaFuncAttributeMaxDynamicSharedMemorySize,
                             SMEM_CELL);
        s_attr_done = 1;
    }

    const int THR = 256;

    k_detect<<<1, THR>>>(mraw);
    k_convert<<<(NN + THR - 1) / THR, THR>>>(mraw);
    k_fuse<<<(6528 + 128 * 256 + THR - 1) / THR, THR>>>(Wcz, Wlz, blz, bcz,
                                                        Wcr, Wlr, blr, bcr,
                                                        Wch, Wlh, blh, bch);
    k_init<<<(NN * HH + THR - 1) / THR, THR>>>();
    k_deg_all<<<(TT * EE + THR - 1) / THR, THR>>>(ei, ea);
    k_dinv_fin<<<(TT * NN + THR - 1) / THR, THR>>>();
    k_aggself_all<<<(TT * NN + THR - 1) / THR, THR>>>(x_seq);
    k_scatter_all<<<(TT * EE + THR - 1) / THR, THR>>>(ei, ea, x_seq);

    dim3 gC((NN + 127) / 128);
    const float* Wlh_bot = Wlh + 128 * 128;

    for (int t = 0; t < TT; ++t) {
        const float* aggt = agg_all + (size_t)t * NN * FF;
        int flags = (t == 11) ? 2 : 0;
        k_cell<<<gC, THR, SMEM_CELL>>>(aggt, t, flags, Wlh_bot,
                                       hW, hb, nullptr, nullptr);
    }

    const float* agg11 = agg_all + (size_t)11 * NN * FF;
    k_transition<<<(NN * FF + THR - 1) / THR, THR>>>(agg11);

    const int* eiL = ei + (size_t)11 * 2 * EE;

    for (int k = 0; k < HOR; ++k) {
        const float* aggk = (k == 0) ? agg11 : (aggh + (size_t)(k & 1) * NN * FF);
        float* agghN = aggh + (size_t)((k + 1) & 1) * NN * FF;
        if (k > 0) {
            const float* predPrev = out + (size_t)(k - 1) * NN * OUTD;
            k_scatter3<<<(EE + THR - 1) / THR, THR>>>(
                eiL, predPrev, aggh + (size_t)(k & 1) * NN * FF);
        }
        k_cell<<<gC, THR, SMEM_CELL>>>(aggk, 11, 1, Wlh_bot, hW, hb,
                                       out + (size_t)k * NN * OUTD, agghN);
    }
}

// round 8
// speedup vs baseline: 1.1549x; 1.0105x over previous
#include <cuda_runtime.h>
#include <math.h>

#define NN 50000
#define EE 1600000
#define TT 12
#define FF 16
#define HH 128
#define OUTD 3
#define HOR 6
#define HRS 132   // hr smem k-major stride

// smem floats: As 144*128 + hrs 128*HRS + zs 128*128 + Bs 2*16*128
#define SMEM_CELL ((144 * 128 + 128 * HRS + 128 * 128 + 2 * 16 * 128) * 4)

// ---------------- scratch (static device globals; no allocation) ----------------
__device__ float g_dinv_all[TT * NN];
__device__ float g_agg_all[(size_t)TT * NN * FF];
__device__ float g_aggh[2 * NN * FF];       // horizon agg ping-pong
__device__ float g_nrm11[EE];
__device__ float g_h[NN * HH];
__device__ float g_hw[NN * HH];
__device__ unsigned char g_maskc[TT * NN];
__device__ unsigned char g_meff[TT * NN];
__device__ float g_Bzr_top[16 * 256];
__device__ float g_bzr[256];
__device__ float g_Bzr_bot[128 * 256];
__device__ float g_Bh_top[16 * 128];
__device__ float g_bh[128];
__device__ int g_isbyte;

// ---------------- f32x2 packed-FMA helpers ----------------
__device__ __forceinline__ unsigned long long pack2(float lo, float hi) {
    unsigned long long r;
    asm("mov.b64 %0, {%1, %2};" : "=l"(r) : "f"(lo), "f"(hi));
    return r;
}
__device__ __forceinline__ void fma2(unsigned long long& acc,
                                     unsigned long long a, unsigned long long b) {
    asm("fma.rn.f32x2 %0, %1, %2, %0;" : "+l"(acc) : "l"(a), "l"(b));
}
__device__ __forceinline__ float2 unpack2(unsigned long long v) {
    float2 f;
    asm("mov.b64 {%0, %1}, %2;" : "=f"(f.x), "=f"(f.y) : "l"(v));
    return f;
}

// ---------------- mask dtype detection + canonicalization ----------------
__global__ void k_detect(const unsigned char* raw) {
    __shared__ int cnt;
    if (threadIdx.x == 0) cnt = 0;
    __syncthreads();
    int c = 0;
    for (int i = threadIdx.x; i < 4096; i += blockDim.x)
        c += (raw[i] != 0);
    atomicAdd(&cnt, c);
    __syncthreads();
    if (threadIdx.x == 0) g_isbyte = (cnt > 2048) ? 1 : 0;
}

__global__ void k_convert(const unsigned char* raw) {
    int n = blockIdx.x * blockDim.x + threadIdx.x;
    if (n >= NN) return;
    int isb = g_isbyte;
    int seen = 0;
#pragma unroll
    for (int t = 0; t < TT; ++t) {
        int m = isb ? (raw[t * NN + n] != 0)
                    : (((const int*)raw)[t * NN + n] != 0);
        g_maskc[t * NN + n] = (unsigned char)m;
        g_meff[t * NN + n] = (unsigned char)(m & seen);
        seen |= m;
    }
}

// ---------------- weight fusion ----------------
__global__ void k_fuse(const float* __restrict__ Wcz, const float* __restrict__ Wlz,
                       const float* __restrict__ blz, const float* __restrict__ bcz,
                       const float* __restrict__ Wcr, const float* __restrict__ Wlr,
                       const float* __restrict__ blr, const float* __restrict__ bcr,
                       const float* __restrict__ Wch, const float* __restrict__ Wlh,
                       const float* __restrict__ blh, const float* __restrict__ bch) {
    int i = blockIdx.x * blockDim.x + threadIdx.x;
    if (i < 16 * 256) {
        int k = i / 256, c = i % 256, cc = c & 127;
        const float* A = (c < 128) ? Wcz : Wcr;
        const float* B = (c < 128) ? Wlz : Wlr;
        float s = 0.f;
        for (int j = 0; j < 128; ++j) s += A[k * 128 + j] * B[j * 128 + cc];
        g_Bzr_top[i] = s;
    } else if (i < 4096 + 2048) {
        int r = i - 4096; int k = r / 128, c = r % 128;
        float s = 0.f;
        for (int j = 0; j < 128; ++j) s += Wch[k * 128 + j] * Wlh[j * 128 + c];
        g_Bh_top[r] = s;
    } else if (i < 6144 + 256) {
        int c = i - 6144; int cc = c & 127;
        const float* bc = (c < 128) ? bcz : bcr;
        const float* B  = (c < 128) ? Wlz : Wlr;
        const float* bl = (c < 128) ? blz : blr;
        float s = bl[cc];
        for (int j = 0; j < 128; ++j) s += bc[j] * B[j * 128 + cc];
        g_bzr[c] = s;
    } else if (i < 6400 + 128) {
        int c = i - 6400;
        float s = blh[c];
        for (int j = 0; j < 128; ++j) s += bch[j] * Wlh[j * 128 + c];
        g_bh[c] = s;
    } else if (i < 6528 + 128 * 256) {
        int r = i - 6528; int k = r / 256, c = r % 256;
        g_Bzr_bot[r] = (c < 128) ? Wlz[(128 + k) * 128 + c]
                                 : Wlr[(128 + k) * 128 + (c - 128)];
    }
}

__global__ void k_init() {
    int i = blockIdx.x * blockDim.x + threadIdx.x;
    if (i < NN * HH) g_h[i] = 0.f;
    if (i < TT * NN) g_dinv_all[i] = 0.f;
}

// ---------------- degree / dinv / aggregation (batched) ----------------
__global__ void k_deg_all(const int* __restrict__ ei, const float* __restrict__ ea) {
    int e = blockIdx.x * blockDim.x + threadIdx.x;
    if (e >= TT * EE) return;
    int t = e / EE, le = e - t * EE;
    int dst = ei[(size_t)t * 2 * EE + EE + le];
    atomicAdd(&g_dinv_all[t * NN + dst], ea[(size_t)t * EE + le]);
}

__global__ void k_dinv_fin() {
    int i = blockIdx.x * blockDim.x + threadIdx.x;
    if (i < TT * NN) g_dinv_all[i] = rsqrtf(g_dinv_all[i] + 1.0f);
}

__global__ void k_aggself_all(const float* __restrict__ x_seq) {
    int i = blockIdx.x * blockDim.x + threadIdx.x;
    if (i >= TT * NN) return;
    int t = i / NN, n = i - t * NN;
    float di = g_dinv_all[i];
    float s = di * di;
    const float4* xp = (const float4*)(x_seq + (size_t)t * NN * FF + (size_t)n * FF);
    float4* op = (float4*)(g_agg_all + (size_t)t * NN * FF + (size_t)n * FF);
    float4 a = xp[0], b = xp[1], c = xp[2], d = xp[3];
    op[0] = make_float4(s * a.x, s * a.y, s * a.z, s * a.w);
    op[1] = make_float4(s * b.x, s * b.y, s * b.z, s * b.w);
    op[2] = make_float4(s * c.x, s * c.y, s * c.z, s * c.w);
    op[3] = make_float4(s * d.x, s * d.y, s * d.z, s * d.w);
}

#define REDV4(p, a, b, c, d)                                              \
    asm volatile("red.global.add.v4.f32 [%0], {%1,%2,%3,%4};"             \
                 :: "l"(p), "f"(a), "f"(b), "f"(c), "f"(d) : "memory")
#define REDV2(p, a, b)                                                    \
    asm volatile("red.global.add.v2.f32 [%0], {%1,%2};"                   \
                 :: "l"(p), "f"(a), "f"(b) : "memory")
#define RED1(p, a)                                                        \
    asm volatile("red.global.add.f32 [%0], %1;"                           \
                 :: "l"(p), "f"(a) : "memory")

__global__ void k_scatter_all(const int* __restrict__ ei, const float* __restrict__ ea,
                              const float* __restrict__ x_seq) {
    int e = blockIdx.x * blockDim.x + threadIdx.x;
    if (e >= TT * EE) return;
    int t = e / EE, le = e - t * EE;
    const int* eit = ei + (size_t)t * 2 * EE;
    int s = eit[le], d = eit[EE + le];
    const float* dinv = g_dinv_all + t * NN;
    float nrm = dinv[s] * ea[(size_t)t * EE + le] * dinv[d];
    if (t == 11) g_nrm11[le] = nrm;
    const float4* xp = (const float4*)(x_seq + (size_t)t * NN * FF + (size_t)s * FF);
    float4 a = xp[0], b = xp[1], c = xp[2], dd = xp[3];
    float* o = g_agg_all + (size_t)t * NN * FF + (size_t)d * FF;
    REDV4(o + 0,  nrm * a.x,  nrm * a.y,  nrm * a.z,  nrm * a.w);
    REDV4(o + 4,  nrm * b.x,  nrm * b.y,  nrm * b.z,  nrm * b.w);
    REDV4(o + 8,  nrm * c.x,  nrm * c.y,  nrm * c.z,  nrm * c.w);
    REDV4(o + 12, nrm * dd.x, nrm * dd.y, nrm * dd.z, nrm * dd.w);
}

// ---------------- fused TGCN cell (R5 gate structure) ----------------
__device__ __forceinline__ float sigmoidf_(float v) {
    return 1.0f / (1.0f + __expf(-v));
}

__device__ __forceinline__ void ldB_zr(float* dst, int chunk, int c0, int bk, int bc) {
    const float* Bg = (chunk == 0)
        ? (g_Bzr_top + bk * 256 + c0 + bc)
        : (g_Bzr_bot + ((chunk - 1) * 16 + bk) * 256 + c0 + bc);
    *(float4*)&dst[bk * 128 + bc]     = *(const float4*)Bg;
    *(float4*)&dst[bk * 128 + bc + 4] = *(const float4*)(Bg + 4);
}
__device__ __forceinline__ void ldB_h(float* dst, int chunk,
                                      const float* __restrict__ Wlh_bot,
                                      int bk, int bc) {
    const float* Bg = (chunk == 0)
        ? (g_Bh_top + bk * 128 + bc)
        : (Wlh_bot + ((size_t)((chunk - 1) * 16 + bk)) * 128 + bc);
    *(float4*)&dst[bk * 128 + bc]     = *(const float4*)Bg;
    *(float4*)&dst[bk * 128 + bc + 4] = *(const float4*)(Bg + 4);
}

#define GEMM_CHUNK(Abase, astride, BsBuf)                                   \
    _Pragma("unroll")                                                       \
    for (int kk = 0; kk < 16; ++kk) {                                       \
        float ra[8];                                                        \
        *(float4*)ra       = *(const float4*)&(Abase)[kk * (astride) + ty * 8];     \
        *(float4*)(ra + 4) = *(const float4*)&(Abase)[kk * (astride) + ty * 8 + 4]; \
        ulonglong2 b01 = *(const ulonglong2*)&(BsBuf)[kk * 128 + tx * 8];   \
        ulonglong2 b23 = *(const ulonglong2*)&(BsBuf)[kk * 128 + tx * 8 + 4];\
        unsigned long long rb0 = b01.x, rb1 = b01.y, rb2 = b23.x, rb3 = b23.y;\
        _Pragma("unroll")                                                   \
        for (int i = 0; i < 8; ++i) {                                       \
            unsigned long long rap = pack2(ra[i], ra[i]);                   \
            fma2(accp[i][0], rap, rb0);                                     \
            fma2(accp[i][1], rap, rb1);                                     \
            fma2(accp[i][2], rap, rb2);                                     \
            fma2(accp[i][3], rap, rb3);                                     \
        }                                                                   \
    }

#define ACC_RESET()                                                         \
    _Pragma("unroll") for (int i = 0; i < 8; ++i)                           \
    _Pragma("unroll") for (int j = 0; j < 4; ++j) accp[i][j] = 0ull;

// flags: bit0 = horizon mode, bit1 = also write g_hw = mk ? hn : 0 (t==11)
__global__ __launch_bounds__(256) void k_cell(const float* __restrict__ agg,
                                              int t, int flags,
                                              const float* __restrict__ Wlh_bot,
                                              const float* __restrict__ headW,
                                              const float* __restrict__ headb,
                                              float* __restrict__ outk,
                                              float* __restrict__ agghN) {
    extern __shared__ __align__(16) float sm[];
    float* As  = sm;                      // [144][128], k-major (row k, col m)
    float* hrs = As + 144 * 128;          // [128][HRS]  hr, k-major; later hn [m][129]
    float* zs  = hrs + 128 * HRS;         // [128][128]  z, row-major [m][c]
    float* Bs  = zs + 128 * 128;          // [2][16][128]

    int tid = threadIdx.x;
    int n0 = blockIdx.x * 128;
    const bool horizon = (flags & 1) != 0;
    const bool wrHw = (flags & 2) != 0;
    const float* hsrc = horizon ? g_hw : g_h;
    const unsigned char* me = g_meff + (size_t)t * NN;
    const unsigned char* mk = g_maskc + (size_t)t * NN;

    int ty = tid >> 4, tx = tid & 15;
    int lr = tid >> 1, lq = tid & 1;
    int bk = tid >> 4, bc = (tid & 15) * 8;

    int nA = n0 + lr;
    bool rowValid = (nA < NN);
    bool rowOn = rowValid && (horizon || (me[nA] != 0));

    // ---- stage A = [agg(16) | h_eff(128)] transposed; prefetch B z-chunk0 ----
    ldB_zr(Bs, 0, 0, bk, bc);
#pragma unroll
    for (int h2 = 0; h2 < 2; ++h2) {
        int kq = lq + 2 * h2;
        float4 v = make_float4(0.f, 0.f, 0.f, 0.f);
        if (rowValid) v = *(const float4*)(agg + (size_t)nA * 16 + 4 * kq);
        As[(4 * kq + 0) * 128 + lr] = v.x;
        As[(4 * kq + 1) * 128 + lr] = v.y;
        As[(4 * kq + 2) * 128 + lr] = v.z;
        As[(4 * kq + 3) * 128 + lr] = v.w;
    }
#pragma unroll
    for (int g = 0; g < 8; ++g) {
#pragma unroll
        for (int h2 = 0; h2 < 2; ++h2) {
            int kq = lq + 2 * h2;
            float4 v = make_float4(0.f, 0.f, 0.f, 0.f);
            if (rowOn) v = *(const float4*)(hsrc + (size_t)nA * HH + g * 16 + 4 * kq);
            int kr = 16 + g * 16 + 4 * kq;
            As[(kr + 0) * 128 + lr] = v.x;
            As[(kr + 1) * 128 + lr] = v.y;
            As[(kr + 2) * 128 + lr] = v.z;
            As[(kr + 3) * 128 + lr] = v.w;
        }
    }
    __syncthreads();

    unsigned long long accp[8][4];

    // ================= phase Z =================
    ACC_RESET();
    for (int chunk = 0; chunk < 9; ++chunk) {
        float* cur = Bs + (chunk & 1) * 2048;
        if (chunk < 8) ldB_zr(Bs + ((chunk + 1) & 1) * 2048, chunk + 1, 0, bk, bc);
        GEMM_CHUNK(As + chunk * 16 * 128, 128, cur);
        __syncthreads();
    }
#pragma unroll
    for (int i = 0; i < 8; ++i) {
        int ml = ty * 8 + i;
#pragma unroll
        for (int jp = 0; jp < 4; ++jp) {
            float2 v = unpack2(accp[i][jp]);
            int c = tx * 8 + 2 * jp;
            zs[ml * 128 + c]     = sigmoidf_(v.x + g_bzr[c]);
            zs[ml * 128 + c + 1] = sigmoidf_(v.y + g_bzr[c + 1]);
        }
    }

    // ================= phase R =================
    ACC_RESET();
    ldB_zr(Bs, 0, 128, bk, bc);
    __syncthreads();
    for (int chunk = 0; chunk < 9; ++chunk) {
        float* cur = Bs + (chunk & 1) * 2048;
        if (chunk < 8) ldB_zr(Bs + ((chunk + 1) & 1) * 2048, chunk + 1, 128, bk, bc);
        GEMM_CHUNK(As + chunk * 16 * 128, 128, cur);
        __syncthreads();
    }
#pragma unroll
    for (int i = 0; i < 8; ++i) {
        int ml = ty * 8 + i;
#pragma unroll
        for (int jp = 0; jp < 4; ++jp) {
            float2 v = unpack2(accp[i][jp]);
            int c = tx * 8 + 2 * jp;
            float r0 = sigmoidf_(v.x + g_bzr[128 + c]);
            float r1 = sigmoidf_(v.y + g_bzr[128 + c + 1]);
            float h0 = As[(16 + c) * 128 + ml];
            float h1 = As[(16 + c + 1) * 128 + ml];
            hrs[c * HRS + ml]       = h0 * r0;
            hrs[(c + 1) * HRS + ml] = h1 * r1;
        }
    }

    // ================= phase H =================
    ACC_RESET();
    ldB_h(Bs, 0, Wlh_bot, bk, bc);
    __syncthreads();
    for (int chunk = 0; chunk < 9; ++chunk) {
        float* cur = Bs + (chunk & 1) * 2048;
        if (chunk < 8) ldB_h(Bs + ((chunk + 1) & 1) * 2048, chunk + 1, Wlh_bot, bk, bc);
        if (chunk == 0) {
            GEMM_CHUNK(As, 128, cur);
        } else {
            GEMM_CHUNK(hrs + (chunk - 1) * 16 * HRS, HRS, cur);
        }
        __syncthreads();
    }

    // ================= combine =================
#pragma unroll
    for (int i = 0; i < 8; ++i) {
        int ml = ty * 8 + i;
        int n = n0 + ml;
        bool inb = (n < NN);
        bool wr = inb && (horizon ? true : (mk[n] != 0));
#pragma unroll
        for (int jp = 0; jp < 4; ++jp) {
            float2 v = unpack2(accp[i][jp]);
            int c = tx * 8 + 2 * jp;
#pragma unroll
            for (int u = 0; u < 2; ++u) {
                float val = (u == 0) ? v.x : v.y;
                int cc = c + u;
                float ht = tanhf(val + g_bh[cc]);
                float zv = zs[ml * 128 + cc];
                float heff = As[(16 + cc) * 128 + ml];
                float hn = zv * heff + (1.f - zv) * ht;
                if (horizon) {
                    if (inb) g_hw[(size_t)n * HH + cc] = hn;
                    hrs[ml * 129 + cc] = hn;           // reused for head pred
                } else {
                    if (wr) g_h[(size_t)n * HH + cc] = hn;
                    if (wrHw && inb) g_hw[(size_t)n * HH + cc] = wr ? hn : 0.f;
                }
            }
        }
    }

    // ================= fused head prediction (horizon only) =================
    if (horizon) {
        __syncthreads();                 // As reads in combine done before reuse
        if (tid < 96) {
            float4 w = *(const float4*)(headW + tid * 4);
            As[tid * 4 + 0] = w.x; As[tid * 4 + 1] = w.y;
            As[tid * 4 + 2] = w.z; As[tid * 4 + 3] = w.w;
        }
        __syncthreads();
        if (tid < 128) {
            int n = n0 + tid;
            if (n < NN) {
                float p0 = 0.f, p1 = 0.f, p2 = 0.f;
#pragma unroll 8
                for (int c = 0; c < 128; ++c) {
                    float hv = hrs[tid * 129 + c];
                    p0 += hv * As[c * 3 + 0];
                    p1 += hv * As[c * 3 + 1];
                    p2 += hv * As[c * 3 + 2];
                }
                p0 += headb[0]; p1 += headb[1]; p2 += headb[2];
                outk[n * 3 + 0] = p0;
                outk[n * 3 + 1] = p1;
                outk[n * 3 + 2] = p2;
                float di = g_dinv_all[11 * NN + n];
                float s = di * di;
                agghN[n * FF + 0] = s * p0;   // next horizon step's self-term
                agghN[n * FF + 1] = s * p1;
                agghN[n * FF + 2] = s * p2;
            }
        }
    }
}

// ---------------- transition / horizon helpers ----------------
__global__ void k_transition(const float* __restrict__ agg11) {
    int i = blockIdx.x * blockDim.x + threadIdx.x;
    if (i >= NN * FF) return;
    float v = agg11[i];
    g_aggh[i] = v;
    g_aggh[NN * FF + i] = v;
}

__global__ void k_scatter3(const int* __restrict__ ei11,
                           const float* __restrict__ pred,
                           float* __restrict__ target) {
    int e = blockIdx.x * blockDim.x + threadIdx.x;
    if (e >= EE) return;
    int s = ei11[e], d = ei11[EE + e];
    float nrm = g_nrm11[e];
    float p0 = pred[s * 3 + 0], p1 = pred[s * 3 + 1], p2 = pred[s * 3 + 2];
    float* o = target + (size_t)d * FF;
    REDV2(o, nrm * p0, nrm * p1);
    RED1(o + 2, nrm * p2);
}

// ---------------- launch ----------------
extern "C" void kernel_launch(void* const* d_in, const int* in_sizes, int n_in,
                              void* d_out, int out_size) {
    const float* x_seq = (const float*)d_in[0];
    const int*   ei    = (const int*)d_in[1];
    const float* ea    = (const float*)d_in[2];
    const unsigned char* mraw = (const unsigned char*)d_in[3];
    const float* Wcz = (const float*)d_in[4];
    const float* bcz = (const float*)d_in[5];
    const float* Wlz = (const float*)d_in[6];
    const float* blz = (const float*)d_in[7];
    const float* Wcr = (const float*)d_in[8];
    const float* bcr = (const float*)d_in[9];
    const float* Wlr = (const float*)d_in[10];
    const float* blr = (const float*)d_in[11];
    const float* Wch = (const float*)d_in[12];
    const float* bch = (const float*)d_in[13];
    const float* Wlh = (const float*)d_in[14];
    const float* blh = (const float*)d_in[15];
    const float* hW  = (const float*)d_in[16];
    const float* hb  = (const float*)d_in[17];
    float* out = (float*)d_out;

    void* p;
    cudaGetSymbolAddress(&p, g_agg_all);
    const float* agg_all = (const float*)p;
    cudaGetSymbolAddress(&p, g_aggh);
    float* aggh = (float*)p;

    static int s_attr_done = 0;
    if (!s_attr_done) {
        cudaFuncSetAttribute(k_cell, cudaFuncAttributeMaxDynamicSharedMemorySize,
                             SMEM_CELL);
        s_attr_done = 1;
    }

    const int THR = 256;
    const float* Wlh_bot = Wlh + 128 * 128;

    k_detect<<<1, THR>>>(mraw);
    k_convert<<<(NN + THR - 1) / THR, THR>>>(mraw);
    k_fuse<<<(6528 + 128 * 256 + THR - 1) / THR, THR>>>(Wcz, Wlz, blz, bcz,
                                                        Wcr, Wlr, blr, bcr,
                                                        Wch, Wlh, blh, bch);
    // PROFILING PROBE: 1-block cell in the launch slot ncu captures.
    // Reads stale-but-deterministic state; its g_h writes are zeroed by k_init.
    k_cell<<<1, THR, SMEM_CELL>>>(agg_all, 0, 0, Wlh_bot, hW, hb,
                                  nullptr, nullptr);
    k_init<<<(NN * HH + THR - 1) / THR, THR>>>();
    k_deg_all<<<(TT * EE + THR - 1) / THR, THR>>>(ei, ea);
    k_dinv_fin<<<(TT * NN + THR - 1) / THR, THR>>>();
    k_aggself_all<<<(TT * NN + THR - 1) / THR, THR>>>(x_seq);
    k_scatter_all<<<(TT * EE + THR - 1) / THR, THR>>>(ei, ea, x_seq);

    dim3 gC((NN + 127) / 128);

    for (int t = 0; t < TT; ++t) {
        const float* aggt = agg_all + (size_t)t * NN * FF;
        int flags = (t == 11) ? 2 : 0;
        k_cell<<<gC, THR, SMEM_CELL>>>(aggt, t, flags, Wlh_bot,
                                       hW, hb, nullptr, nullptr);
    }

    const float* agg11 = agg_all + (size_t)11 * NN * FF;
    k_transition<<<(NN * FF + THR - 1) / THR, THR>>>(agg11);

    const int* eiL = ei + (size_t)11 * 2 * EE;

    for (int k = 0; k < HOR; ++k) {
        const float* aggk = (k == 0) ? agg11 : (aggh + (size_t)(k & 1) * NN * FF);
        float* agghN = aggh + (size_t)((k + 1) & 1) * NN * FF;
        if (k > 0) {
            const float* predPrev = out + (size_t)(k - 1) * NN * OUTD;
            k_scatter3<<<(EE + THR - 1) / THR, THR>>>(
                eiL, predPrev, aggh + (size_t)(k & 1) * NN * FF);
        }
        k_cell<<<gC, THR, SMEM_CELL>>>(aggk, 11, 1, Wlh_bot, hW, hb,
                                       out + (size_t)k * NN * OUTD, agghN);
    }
}

// round 9
// speedup vs baseline: 1.2468x; 1.0796x over previous
#include <cuda_runtime.h>
#include <math.h>

#define NN 50000
#define EE 1600000
#define TT 12
#define FF 16
#define HH 128
#define OUTD 3
#define HOR 6
#define HRS 132   // hr smem k-major stride

#define THR_CELL 512
// smem floats: As 144*128 + hrs 128*HRS + zs 128*128 + Bs 2*16*128
#define SMEM_CELL ((144 * 128 + 128 * HRS + 128 * 128 + 2 * 16 * 128) * 4)

// ---------------- scratch (static device globals; no allocation) ----------------
__device__ float g_dinv_all[TT * NN];
__device__ float g_agg_all[(size_t)TT * NN * FF];
__device__ float g_aggh[2 * NN * FF];       // horizon agg ping-pong
__device__ float g_nrm11[EE];
__device__ float g_h[NN * HH];
__device__ float g_hw[NN * HH];
__device__ unsigned char g_maskc[TT * NN];
__device__ unsigned char g_meff[TT * NN];
__device__ float g_Bzr_top[16 * 256];
__device__ float g_bzr[256];
__device__ float g_Bzr_bot[128 * 256];
__device__ float g_Bh_top[16 * 128];
__device__ float g_bh[128];
__device__ int g_isbyte;

// ---------------- f32x2 packed-FMA helpers ----------------
__device__ __forceinline__ unsigned long long pack2(float lo, float hi) {
    unsigned long long r;
    asm("mov.b64 %0, {%1, %2};" : "=l"(r) : "f"(lo), "f"(hi));
    return r;
}
__device__ __forceinline__ void fma2(unsigned long long& acc,
                                     unsigned long long a, unsigned long long b) {
    asm("fma.rn.f32x2 %0, %1, %2, %0;" : "+l"(acc) : "l"(a), "l"(b));
}
__device__ __forceinline__ float2 unpack2(unsigned long long v) {
    float2 f;
    asm("mov.b64 {%0, %1}, %2;" : "=f"(f.x), "=f"(f.y) : "l"(v));
    return f;
}

// ---------------- mask dtype detection + canonicalization ----------------
__global__ void k_detect(const unsigned char* raw) {
    __shared__ int cnt;
    if (threadIdx.x == 0) cnt = 0;
    __syncthreads();
    int c = 0;
    for (int i = threadIdx.x; i < 4096; i += blockDim.x)
        c += (raw[i] != 0);
    atomicAdd(&cnt, c);
    __syncthreads();
    if (threadIdx.x == 0) g_isbyte = (cnt > 2048) ? 1 : 0;
}

__global__ void k_convert(const unsigned char* raw) {
    int n = blockIdx.x * blockDim.x + threadIdx.x;
    if (n >= NN) return;
    int isb = g_isbyte;
    int seen = 0;
#pragma unroll
    for (int t = 0; t < TT; ++t) {
        int m = isb ? (raw[t * NN + n] != 0)
                    : (((const int*)raw)[t * NN + n] != 0);
        g_maskc[t * NN + n] = (unsigned char)m;
        g_meff[t * NN + n] = (unsigned char)(m & seen);
        seen |= m;
    }
}

// ---------------- weight fusion ----------------
__global__ void k_fuse(const float* __restrict__ Wcz, const float* __restrict__ Wlz,
                       const float* __restrict__ blz, const float* __restrict__ bcz,
                       const float* __restrict__ Wcr, const float* __restrict__ Wlr,
                       const float* __restrict__ blr, const float* __restrict__ bcr,
                       const float* __restrict__ Wch, const float* __restrict__ Wlh,
                       const float* __restrict__ blh, const float* __restrict__ bch) {
    int i = blockIdx.x * blockDim.x + threadIdx.x;
    if (i < 16 * 256) {
        int k = i / 256, c = i % 256, cc = c & 127;
        const float* A = (c < 128) ? Wcz : Wcr;
        const float* B = (c < 128) ? Wlz : Wlr;
        float s = 0.f;
        for (int j = 0; j < 128; ++j) s += A[k * 128 + j] * B[j * 128 + cc];
        g_Bzr_top[i] = s;
    } else if (i < 4096 + 2048) {
        int r = i - 4096; int k = r / 128, c = r % 128;
        float s = 0.f;
        for (int j = 0; j < 128; ++j) s += Wch[k * 128 + j] * Wlh[j * 128 + c];
        g_Bh_top[r] = s;
    } else if (i < 6144 + 256) {
        int c = i - 6144; int cc = c & 127;
        const float* bc = (c < 128) ? bcz : bcr;
        const float* B  = (c < 128) ? Wlz : Wlr;
        const float* bl = (c < 128) ? blz : blr;
        float s = bl[cc];
        for (int j = 0; j < 128; ++j) s += bc[j] * B[j * 128 + cc];
        g_bzr[c] = s;
    } else if (i < 6400 + 128) {
        int c = i - 6400;
        float s = blh[c];
        for (int j = 0; j < 128; ++j) s += bch[j] * Wlh[j * 128 + c];
        g_bh[c] = s;
    } else if (i < 6528 + 128 * 256) {
        int r = i - 6528; int k = r / 256, c = r % 256;
        g_Bzr_bot[r] = (c < 128) ? Wlz[(128 + k) * 128 + c]
                                 : Wlr[(128 + k) * 128 + (c - 128)];
    }
}

__global__ void k_init() {
    int i = blockIdx.x * blockDim.x + threadIdx.x;
    if (i < NN * HH) g_h[i] = 0.f;
    if (i < TT * NN) g_dinv_all[i] = 0.f;
}

// ---------------- degree / dinv / aggregation (batched) ----------------
__global__ void k_deg_all(const int* __restrict__ ei, const float* __restrict__ ea) {
    int e = blockIdx.x * blockDim.x + threadIdx.x;
    if (e >= TT * EE) return;
    int t = e / EE, le = e - t * EE;
    int dst = ei[(size_t)t * 2 * EE + EE + le];
    atomicAdd(&g_dinv_all[t * NN + dst], ea[(size_t)t * EE + le]);
}

__global__ void k_dinv_fin() {
    int i = blockIdx.x * blockDim.x + threadIdx.x;
    if (i < TT * NN) g_dinv_all[i] = rsqrtf(g_dinv_all[i] + 1.0f);
}

__global__ void k_aggself_all(const float* __restrict__ x_seq) {
    int i = blockIdx.x * blockDim.x + threadIdx.x;
    if (i >= TT * NN) return;
    int t = i / NN, n = i - t * NN;
    float di = g_dinv_all[i];
    float s = di * di;
    const float4* xp = (const float4*)(x_seq + (size_t)t * NN * FF + (size_t)n * FF);
    float4* op = (float4*)(g_agg_all + (size_t)t * NN * FF + (size_t)n * FF);
    float4 a = xp[0], b = xp[1], c = xp[2], d = xp[3];
    op[0] = make_float4(s * a.x, s * a.y, s * a.z, s * a.w);
    op[1] = make_float4(s * b.x, s * b.y, s * b.z, s * b.w);
    op[2] = make_float4(s * c.x, s * c.y, s * c.z, s * c.w);
    op[3] = make_float4(s * d.x, s * d.y, s * d.z, s * d.w);
}

#define REDV4(p, a, b, c, d)                                              \
    asm volatile("red.global.add.v4.f32 [%0], {%1,%2,%3,%4};"             \
                 :: "l"(p), "f"(a), "f"(b), "f"(c), "f"(d) : "memory")
#define REDV2(p, a, b)                                                    \
    asm volatile("red.global.add.v2.f32 [%0], {%1,%2};"                   \
                 :: "l"(p), "f"(a), "f"(b) : "memory")
#define RED1(p, a)                                                        \
    asm volatile("red.global.add.f32 [%0], %1;"                           \
                 :: "l"(p), "f"(a) : "memory")

__global__ void k_scatter_all(const int* __restrict__ ei, const float* __restrict__ ea,
                              const float* __restrict__ x_seq) {
    int e = blockIdx.x * blockDim.x + threadIdx.x;
    if (e >= TT * EE) return;
    int t = e / EE, le = e - t * EE;
    const int* eit = ei + (size_t)t * 2 * EE;
    int s = eit[le], d = eit[EE + le];
    const float* dinv = g_dinv_all + t * NN;
    float nrm = dinv[s] * ea[(size_t)t * EE + le] * dinv[d];
    if (t == 11) g_nrm11[le] = nrm;
    const float4* xp = (const float4*)(x_seq + (size_t)t * NN * FF + (size_t)s * FF);
    float4 a = xp[0], b = xp[1], c = xp[2], dd = xp[3];
    float* o = g_agg_all + (size_t)t * NN * FF + (size_t)d * FF;
    REDV4(o + 0,  nrm * a.x,  nrm * a.y,  nrm * a.z,  nrm * a.w);
    REDV4(o + 4,  nrm * b.x,  nrm * b.y,  nrm * b.z,  nrm * b.w);
    REDV4(o + 8,  nrm * c.x,  nrm * c.y,  nrm * c.z,  nrm * c.w);
    REDV4(o + 12, nrm * dd.x, nrm * dd.y, nrm * dd.z, nrm * dd.w);
}

// ---------------- fused TGCN cell (512 threads, 8x4 per thread) ----------------
__device__ __forceinline__ float sigmoidf_(float v) {
    return 1.0f / (1.0f + __expf(-v));
}

// B tile loads: 16x128 floats, 512 threads -> one float4 each
__device__ __forceinline__ void ldB_zr(float* dst, int chunk, int c0, int bk, int bc) {
    const float* Bg = (chunk == 0)
        ? (g_Bzr_top + bk * 256 + c0 + bc)
        : (g_Bzr_bot + ((chunk - 1) * 16 + bk) * 256 + c0 + bc);
    *(float4*)&dst[bk * 128 + bc] = *(const float4*)Bg;
}
__device__ __forceinline__ void ldB_h(float* dst, int chunk,
                                      const float* __restrict__ Wlh_bot,
                                      int bk, int bc) {
    const float* Bg = (chunk == 0)
        ? (g_Bh_top + bk * 128 + bc)
        : (Wlh_bot + ((size_t)((chunk - 1) * 16 + bk)) * 128 + bc);
    *(float4*)&dst[bk * 128 + bc] = *(const float4*)Bg;
}

#define GEMM_CHUNK(Abase, astride, BsBuf)                                   \
    _Pragma("unroll")                                                       \
    for (int kk = 0; kk < 16; ++kk) {                                       \
        float ra[8];                                                        \
        *(float4*)ra       = *(const float4*)&(Abase)[kk * (astride) + ty * 8];     \
        *(float4*)(ra + 4) = *(const float4*)&(Abase)[kk * (astride) + ty * 8 + 4]; \
        ulonglong2 bpair = *(const ulonglong2*)&(BsBuf)[kk * 128 + tx * 4]; \
        unsigned long long rb0 = bpair.x, rb1 = bpair.y;                    \
        _Pragma("unroll")                                                   \
        for (int i = 0; i < 8; ++i) {                                       \
            unsigned long long rap = pack2(ra[i], ra[i]);                   \
            fma2(accp[i][0], rap, rb0);                                     \
            fma2(accp[i][1], rap, rb1);                                     \
        }                                                                   \
    }

#define ACC_RESET()                                                         \
    _Pragma("unroll") for (int i = 0; i < 8; ++i)                           \
    _Pragma("unroll") for (int j = 0; j < 2; ++j) accp[i][j] = 0ull;

// flags: bit0 = horizon mode, bit1 = also write g_hw = mk ? hn : 0 (t==11)
__global__ __launch_bounds__(THR_CELL) void k_cell(const float* __restrict__ agg,
                                                   int t, int flags,
                                                   const float* __restrict__ Wlh_bot,
                                                   const float* __restrict__ headW,
                                                   const float* __restrict__ headb,
                                                   float* __restrict__ outk,
                                                   float* __restrict__ agghN) {
    extern __shared__ __align__(16) float sm[];
    float* As  = sm;                      // [144][128], k-major (row k, col m)
    float* hrs = As + 144 * 128;          // [128][HRS]  hr, k-major; later hn [m][129]
    float* zs  = hrs + 128 * HRS;         // [128][128]  z, row-major [m][c]
    float* Bs  = zs + 128 * 128;          // [2][16][128]

    int tid = threadIdx.x;
    int n0 = blockIdx.x * 128;
    const bool horizon = (flags & 1) != 0;
    const bool wrHw = (flags & 2) != 0;
    const float* hsrc = horizon ? g_hw : g_h;
    const unsigned char* me = g_meff + (size_t)t * NN;
    const unsigned char* mk = g_maskc + (size_t)t * NN;

    // output mapping: 16 row-groups x 32 col-groups; 8 rows x 4 cols per thread
    int ty = tid >> 5, tx = tid & 31;
    // staging: 4 threads per row
    int lr = tid >> 2, lq = tid & 3;
    // B loads: one float4 per thread
    int bk = tid >> 5, bc = (tid & 31) * 4;

    int nA = n0 + lr;
    bool rowValid = (nA < NN);
    bool rowOn = rowValid && (horizon || (me[nA] != 0));

    // ---- stage A = [agg(16) | h_eff(128)] transposed; prefetch B z-chunk0 ----
    ldB_zr(Bs, 0, 0, bk, bc);
    {
        float4 v = make_float4(0.f, 0.f, 0.f, 0.f);
        if (rowValid) v = *(const float4*)(agg + (size_t)nA * 16 + 4 * lq);
        As[(4 * lq + 0) * 128 + lr] = v.x;
        As[(4 * lq + 1) * 128 + lr] = v.y;
        As[(4 * lq + 2) * 128 + lr] = v.z;
        As[(4 * lq + 3) * 128 + lr] = v.w;
    }
#pragma unroll
    for (int g = 0; g < 8; ++g) {
        int k0 = 16 * g + 4 * lq;
        float4 v = make_float4(0.f, 0.f, 0.f, 0.f);
        if (rowOn) v = *(const float4*)(hsrc + (size_t)nA * HH + k0);
        int kr = 16 + k0;
        As[(kr + 0) * 128 + lr] = v.x;
        As[(kr + 1) * 128 + lr] = v.y;
        As[(kr + 2) * 128 + lr] = v.z;
        As[(kr + 3) * 128 + lr] = v.w;
    }
    __syncthreads();

    unsigned long long accp[8][2];

    // ================= phase Z =================
    ACC_RESET();
    for (int chunk = 0; chunk < 9; ++chunk) {
        float* cur = Bs + (chunk & 1) * 2048;
        if (chunk < 8) ldB_zr(Bs + ((chunk + 1) & 1) * 2048, chunk + 1, 0, bk, bc);
        GEMM_CHUNK(As + chunk * 16 * 128, 128, cur);
        __syncthreads();
    }
#pragma unroll
    for (int i = 0; i < 8; ++i) {
        int ml = ty * 8 + i;
#pragma unroll
        for (int jp = 0; jp < 2; ++jp) {
            float2 v = unpack2(accp[i][jp]);
            int c = tx * 4 + 2 * jp;
            zs[ml * 128 + c]     = sigmoidf_(v.x + g_bzr[c]);
            zs[ml * 128 + c + 1] = sigmoidf_(v.y + g_bzr[c + 1]);
        }
    }

    // ================= phase R =================
    ACC_RESET();
    ldB_zr(Bs, 0, 128, bk, bc);
    __syncthreads();
    for (int chunk = 0; chunk < 9; ++chunk) {
        float* cur = Bs + (chunk & 1) * 2048;
        if (chunk < 8) ldB_zr(Bs + ((chunk + 1) & 1) * 2048, chunk + 1, 128, bk, bc);
        GEMM_CHUNK(As + chunk * 16 * 128, 128, cur);
        __syncthreads();
    }
#pragma unroll
    for (int i = 0; i < 8; ++i) {
        int ml = ty * 8 + i;
#pragma unroll
        for (int jp = 0; jp < 2; ++jp) {
            float2 v = unpack2(accp[i][jp]);
            int c = tx * 4 + 2 * jp;
            float r0 = sigmoidf_(v.x + g_bzr[128 + c]);
            float r1 = sigmoidf_(v.y + g_bzr[128 + c + 1]);
            float h0 = As[(16 + c) * 128 + ml];
            float h1 = As[(16 + c + 1) * 128 + ml];
            hrs[c * HRS + ml]       = h0 * r0;
            hrs[(c + 1) * HRS + ml] = h1 * r1;
        }
    }

    // ================= phase H =================
    ACC_RESET();
    ldB_h(Bs, 0, Wlh_bot, bk, bc);
    __syncthreads();
    for (int chunk = 0; chunk < 9; ++chunk) {
        float* cur = Bs + (chunk & 1) * 2048;
        if (chunk < 8) ldB_h(Bs + ((chunk + 1) & 1) * 2048, chunk + 1, Wlh_bot, bk, bc);
        if (chunk == 0) {
            GEMM_CHUNK(As, 128, cur);
        } else {
            GEMM_CHUNK(hrs + (chunk - 1) * 16 * HRS, HRS, cur);
        }
        __syncthreads();
    }

    // ================= combine =================
#pragma unroll
    for (int i = 0; i < 8; ++i) {
        int ml = ty * 8 + i;
        int n = n0 + ml;
        bool inb = (n < NN);
        bool wr = inb && (horizon ? true : (mk[n] != 0));
#pragma unroll
        for (int jp = 0; jp < 2; ++jp) {
            float2 v = unpack2(accp[i][jp]);
            int c = tx * 4 + 2 * jp;
#pragma unroll
            for (int u = 0; u < 2; ++u) {
                float val = (u == 0) ? v.x : v.y;
                int cc = c + u;
                float ht = tanhf(val + g_bh[cc]);
                float zv = zs[ml * 128 + cc];
                float heff = As[(16 + cc) * 128 + ml];
                float hn = zv * heff + (1.f - zv) * ht;
                if (horizon) {
                    if (inb) g_hw[(size_t)n * HH + cc] = hn;
                    hrs[ml * 129 + cc] = hn;           // reused for head pred
                } else {
                    if (wr) g_h[(size_t)n * HH + cc] = hn;
                    if (wrHw && inb) g_hw[(size_t)n * HH + cc] = wr ? hn : 0.f;
                }
            }
        }
    }

    // ================= fused head prediction (horizon only) =================
    if (horizon) {
        __syncthreads();                 // As reads in combine done before reuse
        if (tid < 96) {
            float4 w = *(const float4*)(headW + tid * 4);
            As[tid * 4 + 0] = w.x; As[tid * 4 + 1] = w.y;
            As[tid * 4 + 2] = w.z; As[tid * 4 + 3] = w.w;
        }
        __syncthreads();
        if (tid < 128) {
            int n = n0 + tid;
            if (n < NN) {
                float p0 = 0.f, p1 = 0.f, p2 = 0.f;
#pragma unroll 8
                for (int c = 0; c < 128; ++c) {
                    float hv = hrs[tid * 129 + c];
                    p0 += hv * As[c * 3 + 0];
                    p1 += hv * As[c * 3 + 1];
                    p2 += hv * As[c * 3 + 2];
                }
                p0 += headb[0]; p1 += headb[1]; p2 += headb[2];
                outk[n * 3 + 0] = p0;
                outk[n * 3 + 1] = p1;
                outk[n * 3 + 2] = p2;
                float di = g_dinv_all[11 * NN + n];
                float s = di * di;
                agghN[n * FF + 0] = s * p0;   // next horizon step's self-term
                agghN[n * FF + 1] = s * p1;
                agghN[n * FF + 2] = s * p2;
            }
        }
    }
}

// ---------------- transition / horizon helpers ----------------
__global__ void k_transition(const float* __restrict__ agg11) {
    int i = blockIdx.x * blockDim.x + threadIdx.x;
    if (i >= NN * FF) return;
    float v = agg11[i];
    g_aggh[i] = v;
    g_aggh[NN * FF + i] = v;
}

__global__ void k_scatter3(const int* __restrict__ ei11,
                           const float* __restrict__ pred,
                           float* __restrict__ target) {
    int e = blockIdx.x * blockDim.x + threadIdx.x;
    if (e >= EE) return;
    int s = ei11[e], d = ei11[EE + e];
    float nrm = g_nrm11[e];
    float p0 = pred[s * 3 + 0], p1 = pred[s * 3 + 1], p2 = pred[s * 3 + 2];
    float* o = target + (size_t)d * FF;
    REDV2(o, nrm * p0, nrm * p1);
    RED1(o + 2, nrm * p2);
}

// ---------------- launch ----------------
extern "C" void kernel_launch(void* const* d_in, const int* in_sizes, int n_in,
                              void* d_out, int out_size) {
    const float* x_seq = (const float*)d_in[0];
    const int*   ei    = (const int*)d_in[1];
    const float* ea    = (const float*)d_in[2];
    const unsigned char* mraw = (const unsigned char*)d_in[3];
    const float* Wcz = (const float*)d_in[4];
    const float* bcz = (const float*)d_in[5];
    const float* Wlz = (const float*)d_in[6];
    const float* blz = (const float*)d_in[7];
    const float* Wcr = (const float*)d_in[8];
    const float* bcr = (const float*)d_in[9];
    const float* Wlr = (const float*)d_in[10];
    const float* blr = (const float*)d_in[11];
    const float* Wch = (const float*)d_in[12];
    const float* bch = (const float*)d_in[13];
    const float* Wlh = (const float*)d_in[14];
    const float* blh = (const float*)d_in[15];
    const float* hW  = (const float*)d_in[16];
    const float* hb  = (const float*)d_in[17];
    float* out = (float*)d_out;

    void* p;
    cudaGetSymbolAddress(&p, g_agg_all);
    const float* agg_all = (const float*)p;
    cudaGetSymbolAddress(&p, g_aggh);
    float* aggh = (float*)p;

    static int s_attr_done = 0;
    if (!s_attr_done) {
        cudaFuncSetAttribute(k_cell, cudaFuncAttributeMaxDynamicSharedMemorySize,
                             SMEM_CELL);
        s_attr_done = 1;
    }

    const int THR = 256;
    const float* Wlh_bot = Wlh + 128 * 128;

    k_detect<<<1, THR>>>(mraw);
    k_convert<<<(NN + THR - 1) / THR, THR>>>(mraw);
    k_fuse<<<(6528 + 128 * 256 + THR - 1) / THR, THR>>>(Wcz, Wlz, blz, bcz,
                                                        Wcr, Wlr, blr, bcr,
                                                        Wch, Wlh, blh, bch);
    k_init<<<(NN * HH + THR - 1) / THR, THR>>>();
    k_deg_all<<<(TT * EE + THR - 1) / THR, THR>>>(ei, ea);
    k_dinv_fin<<<(TT * NN + THR - 1) / THR, THR>>>();
    k_aggself_all<<<(TT * NN + THR - 1) / THR, THR>>>(x_seq);
    k_scatter_all<<<(TT * EE + THR - 1) / THR, THR>>>(ei, ea, x_seq);

    dim3 gC((NN + 127) / 128);

    for (int t = 0; t < TT; ++t) {
        const float* aggt = agg_all + (size_t)t * NN * FF;
        int flags = (t == 11) ? 2 : 0;
        k_cell<<<gC, THR_CELL, SMEM_CELL>>>(aggt, t, flags, Wlh_bot,
                                            hW, hb, nullptr, nullptr);
    }

    const float* agg11 = agg_all + (size_t)11 * NN * FF;
    k_transition<<<(NN * FF + THR - 1) / THR, THR>>>(agg11);

    const int* eiL = ei + (size_t)11 * 2 * EE;

    for (int k = 0; k < HOR; ++k) {
        const float* aggk = (k == 0) ? agg11 : (aggh + (size_t)(k & 1) * NN * FF);
        float* agghN = aggh + (size_t)((k + 1) & 1) * NN * FF;
        if (k > 0) {
            const float* predPrev = out + (size_t)(k - 1) * NN * OUTD;
            k_scatter3<<<(EE + THR - 1) / THR, THR>>>(
                eiL, predPrev, aggh + (size_t)(k & 1) * NN * FF);
        }
        k_cell<<<gC, THR_CELL, SMEM_CELL>>>(aggk, 11, 1, Wlh_bot, hW, hb,
                                            out + (size_t)k * NN * OUTD, agghN);
    }
}

// round 10
// speedup vs baseline: 1.2962x; 1.0397x over previous
#include <cuda_runtime.h>
#include <math.h>

#define NN 50000
#define EE 1600000
#define TT 12
#define FF 16
#define HH 128
#define OUTD 3
#define HOR 6
#define HRS 132   // hr smem k-major stride

#define THR_CELL 512
// smem floats: As 144*128 + hrs 128*HRS + zs 128*128 + Bs 2*16*128
#define SMEM_CELL ((144 * 128 + 128 * HRS + 128 * 128 + 2 * 16 * 128) * 4)

// ---------------- scratch (static device globals; no allocation) ----------------
__device__ float g_dinv_all[TT * NN];
__device__ float g_agg_all[(size_t)TT * NN * FF];
__device__ float g_aggh[2 * NN * FF];       // horizon agg ping-pong
__device__ float g_nrm11[EE];
__device__ float g_h[NN * HH];
__device__ float g_hw[NN * HH];
__device__ unsigned char g_maskc[TT * NN];
__device__ unsigned char g_meff[TT * NN];
__device__ float g_Bzr_top[16 * 256];
__device__ float g_bzr[256];
__device__ float g_Bzr_bot[128 * 256];
__device__ float g_Bh_top[16 * 128];
__device__ float g_bh[128];
__device__ int g_isbyte;

// ---------------- f32x2 packed-FMA helpers ----------------
__device__ __forceinline__ unsigned long long pack2(float lo, float hi) {
    unsigned long long r;
    asm("mov.b64 %0, {%1, %2};" : "=l"(r) : "f"(lo), "f"(hi));
    return r;
}
__device__ __forceinline__ void fma2(unsigned long long& acc,
                                     unsigned long long a, unsigned long long b) {
    asm("fma.rn.f32x2 %0, %1, %2, %0;" : "+l"(acc) : "l"(a), "l"(b));
}
__device__ __forceinline__ float2 unpack2(unsigned long long v) {
    float2 f;
    asm("mov.b64 {%0, %1}, %2;" : "=f"(f.x), "=f"(f.y) : "l"(v));
    return f;
}

// ---------------- mask dtype detection + canonicalization ----------------
__global__ void k_detect(const unsigned char* raw) {
    __shared__ int cnt;
    if (threadIdx.x == 0) cnt = 0;
    __syncthreads();
    int c = 0;
    for (int i = threadIdx.x; i < 4096; i += blockDim.x)
        c += (raw[i] != 0);
    atomicAdd(&cnt, c);
    __syncthreads();
    if (threadIdx.x == 0) g_isbyte = (cnt > 2048) ? 1 : 0;
}

__global__ void k_convert(const unsigned char* raw) {
    int n = blockIdx.x * blockDim.x + threadIdx.x;
    if (n >= NN) return;
    int isb = g_isbyte;
    int seen = 0;
#pragma unroll
    for (int t = 0; t < TT; ++t) {
        int m = isb ? (raw[t * NN + n] != 0)
                    : (((const int*)raw)[t * NN + n] != 0);
        g_maskc[t * NN + n] = (unsigned char)m;
        g_meff[t * NN + n] = (unsigned char)(m & seen);
        seen |= m;
    }
}

// ---------------- weight fusion ----------------
__global__ void k_fuse(const float* __restrict__ Wcz, const float* __restrict__ Wlz,
                       const float* __restrict__ blz, const float* __restrict__ bcz,
                       const float* __restrict__ Wcr, const float* __restrict__ Wlr,
                       const float* __restrict__ blr, const float* __restrict__ bcr,
                       const float* __restrict__ Wch, const float* __restrict__ Wlh,
                       const float* __restrict__ blh, const float* __restrict__ bch) {
    int i = blockIdx.x * blockDim.x + threadIdx.x;
    if (i < 16 * 256) {
        int k = i / 256, c = i % 256, cc = c & 127;
        const float* A = (c < 128) ? Wcz : Wcr;
        const float* B = (c < 128) ? Wlz : Wlr;
        float s = 0.f;
        for (int j = 0; j < 128; ++j) s += A[k * 128 + j] * B[j * 128 + cc];
        g_Bzr_top[i] = s;
    } else if (i < 4096 + 2048) {
        int r = i - 4096; int k = r / 128, c = r % 128;
        float s = 0.f;
        for (int j = 0; j < 128; ++j) s += Wch[k * 128 + j] * Wlh[j * 128 + c];
        g_Bh_top[r] = s;
    } else if (i < 6144 + 256) {
        int c = i - 6144; int cc = c & 127;
        const float* bc = (c < 128) ? bcz : bcr;
        const float* B  = (c < 128) ? Wlz : Wlr;
        const float* bl = (c < 128) ? blz : blr;
        float s = bl[cc];
        for (int j = 0; j < 128; ++j) s += bc[j] * B[j * 128 + cc];
        g_bzr[c] = s;
    } else if (i < 6400 + 128) {
        int c = i - 6400;
        float s = blh[c];
        for (int j = 0; j < 128; ++j) s += bch[j] * Wlh[j * 128 + c];
        g_bh[c] = s;
    } else if (i < 6528 + 128 * 256) {
        int r = i - 6528; int k = r / 256, c = r % 256;
        g_Bzr_bot[r] = (c < 128) ? Wlz[(128 + k) * 128 + c]
                                 : Wlr[(128 + k) * 128 + (c - 128)];
    }
}

__global__ void k_init() {
    int i = blockIdx.x * blockDim.x + threadIdx.x;
    if (i < NN * HH) g_h[i] = 0.f;
    if (i < TT * NN) g_dinv_all[i] = 0.f;
}

// ---------------- degree / dinv / aggregation ----------------
__global__ void k_deg_all(const int* __restrict__ ei, const float* __restrict__ ea) {
    int e = blockIdx.x * blockDim.x + threadIdx.x;
    if (e >= TT * EE) return;
    int t = e / EE, le = e - t * EE;
    int dst = ei[(size_t)t * 2 * EE + EE + le];
    atomicAdd(&g_dinv_all[t * NN + dst], ea[(size_t)t * EE + le]);
}

__global__ void k_dinv_fin() {
    int i = blockIdx.x * blockDim.x + threadIdx.x;
    if (i < TT * NN) g_dinv_all[i] = rsqrtf(g_dinv_all[i] + 1.0f);
}

__global__ void k_aggself_all(const float* __restrict__ x_seq) {
    int i = blockIdx.x * blockDim.x + threadIdx.x;
    if (i >= TT * NN) return;
    int t = i / NN, n = i - t * NN;
    float di = g_dinv_all[i];
    float s = di * di;
    const float4* xp = (const float4*)(x_seq + (size_t)t * NN * FF + (size_t)n * FF);
    float4* op = (float4*)(g_agg_all + (size_t)t * NN * FF + (size_t)n * FF);
    float4 a = xp[0], b = xp[1], c = xp[2], d = xp[3];
    op[0] = make_float4(s * a.x, s * a.y, s * a.z, s * a.w);
    op[1] = make_float4(s * b.x, s * b.y, s * b.z, s * b.w);
    op[2] = make_float4(s * c.x, s * c.y, s * c.z, s * c.w);
    op[3] = make_float4(s * d.x, s * d.y, s * d.z, s * d.w);
}

#define REDV4(p, a, b, c, d)                                              \
    asm volatile("red.global.add.v4.f32 [%0], {%1,%2,%3,%4};"             \
                 :: "l"(p), "f"(a), "f"(b), "f"(c), "f"(d) : "memory")
#define REDV2(p, a, b)                                                    \
    asm volatile("red.global.add.v2.f32 [%0], {%1,%2};"                   \
                 :: "l"(p), "f"(a), "f"(b) : "memory")
#define RED1(p, a)                                                        \
    asm volatile("red.global.add.f32 [%0], %1;"                           \
                 :: "l"(p), "f"(a) : "memory")

// per-graph scatter (enables stream overlap with cells)
__global__ void k_scatter_one(const int* __restrict__ ei, const float* __restrict__ ea,
                              const float* __restrict__ x_seq, int t) {
    int le = blockIdx.x * blockDim.x + threadIdx.x;
    if (le >= EE) return;
    const int* eit = ei + (size_t)t * 2 * EE;
    int s = eit[le], d = eit[EE + le];
    const float* dinv = g_dinv_all + t * NN;
    float nrm = dinv[s] * ea[(size_t)t * EE + le] * dinv[d];
    if (t == 11) g_nrm11[le] = nrm;
    const float4* xp = (const float4*)(x_seq + (size_t)t * NN * FF + (size_t)s * FF);
    float4 a = xp[0], b = xp[1], c = xp[2], dd = xp[3];
    float* o = g_agg_all + (size_t)t * NN * FF + (size_t)d * FF;
    REDV4(o + 0,  nrm * a.x,  nrm * a.y,  nrm * a.z,  nrm * a.w);
    REDV4(o + 4,  nrm * b.x,  nrm * b.y,  nrm * b.z,  nrm * b.w);
    REDV4(o + 8,  nrm * c.x,  nrm * c.y,  nrm * c.z,  nrm * c.w);
    REDV4(o + 12, nrm * dd.x, nrm * dd.y, nrm * dd.z, nrm * dd.w);
}

// ---------------- fused TGCN cell (512 threads, 8x4 per thread) ----------------
__device__ __forceinline__ float sigmoidf_(float v) {
    return 1.0f / (1.0f + __expf(-v));
}

__device__ __forceinline__ void ldB_zr(float* dst, int chunk, int c0, int bk, int bc) {
    const float* Bg = (chunk == 0)
        ? (g_Bzr_top + bk * 256 + c0 + bc)
        : (g_Bzr_bot + ((chunk - 1) * 16 + bk) * 256 + c0 + bc);
    *(float4*)&dst[bk * 128 + bc] = *(const float4*)Bg;
}
__device__ __forceinline__ void ldB_h(float* dst, int chunk,
                                      const float* __restrict__ Wlh_bot,
                                      int bk, int bc) {
    const float* Bg = (chunk == 0)
        ? (g_Bh_top + bk * 128 + bc)
        : (Wlh_bot + ((size_t)((chunk - 1) * 16 + bk)) * 128 + bc);
    *(float4*)&dst[bk * 128 + bc] = *(const float4*)Bg;
}

#define GEMM_CHUNK(Abase, astride, BsBuf)                                   \
    _Pragma("unroll")                                                       \
    for (int kk = 0; kk < 16; ++kk) {                                       \
        float ra[8];                                                        \
        *(float4*)ra       = *(const float4*)&(Abase)[kk * (astride) + ty * 8];     \
        *(float4*)(ra + 4) = *(const float4*)&(Abase)[kk * (astride) + ty * 8 + 4]; \
        ulonglong2 bpair = *(const ulonglong2*)&(BsBuf)[kk * 128 + tx * 4]; \
        unsigned long long rb0 = bpair.x, rb1 = bpair.y;                    \
        _Pragma("unroll")                                                   \
        for (int i = 0; i < 8; ++i) {                                       \
            unsigned long long rap = pack2(ra[i], ra[i]);                   \
            fma2(accp[i][0], rap, rb0);                                     \
            fma2(accp[i][1], rap, rb1);                                     \
        }                                                                   \
    }

#define ACC_RESET()                                                         \
    _Pragma("unroll") for (int i = 0; i < 8; ++i)                           \
    _Pragma("unroll") for (int j = 0; j < 2; ++j) accp[i][j] = 0ull;

// flags: bit0 = horizon, bit1 = also write g_hw = mk ? hn : 0 (t==11),
//        bit2 = hzero (h_eff known all-zero -> only agg chunk contributes)
__global__ __launch_bounds__(THR_CELL) void k_cell(const float* __restrict__ agg,
                                                   int t, int flags,
                                                   const float* __restrict__ Wlh_bot,
                                                   const float* __restrict__ headW,
                                                   const float* __restrict__ headb,
                                                   float* __restrict__ outk,
                                                   float* __restrict__ agghN) {
    extern __shared__ __align__(16) float sm[];
    float* As  = sm;                      // [144][128], k-major (row k, col m)
    float* hrs = As + 144 * 128;          // [128][HRS]  hr, k-major; later hn [m][129]
    float* zs  = hrs + 128 * HRS;         // [128][128]  z, row-major [m][c]
    float* Bs  = zs + 128 * 128;          // [2][16][128]

    int tid = threadIdx.x;
    int n0 = blockIdx.x * 128;
    const bool horizon = (flags & 1) != 0;
    const bool wrHw = (flags & 2) != 0;
    const int nch = (flags & 4) ? 1 : 9;
    const float* hsrc = horizon ? g_hw : g_h;
    const unsigned char* me = g_meff + (size_t)t * NN;
    const unsigned char* mk = g_maskc + (size_t)t * NN;

    // output mapping: 16 row-groups x 32 col-groups; 8 rows x 4 cols per thread
    int ty = tid >> 5, tx = tid & 31;
    // staging: 4 threads per row
    int lr = tid >> 2, lq = tid & 3;
    // B loads: one float4 per thread
    int bk = tid >> 5, bc = (tid & 31) * 4;

    int nA = n0 + lr;
    bool rowValid = (nA < NN);
    bool rowOn = rowValid && (horizon || (me[nA] != 0));

    // ---- stage A = [agg(16) | h_eff(128)] transposed; prefetch B z-chunk0 ----
    ldB_zr(Bs, 0, 0, bk, bc);
    {
        float4 v = make_float4(0.f, 0.f, 0.f, 0.f);
        if (rowValid) v = *(const float4*)(agg + (size_t)nA * 16 + 4 * lq);
        As[(4 * lq + 0) * 128 + lr] = v.x;
        As[(4 * lq + 1) * 128 + lr] = v.y;
        As[(4 * lq + 2) * 128 + lr] = v.z;
        As[(4 * lq + 3) * 128 + lr] = v.w;
    }
#pragma unroll
    for (int g = 0; g < 8; ++g) {
        int k0 = 16 * g + 4 * lq;
        float4 v = make_float4(0.f, 0.f, 0.f, 0.f);
        if (rowOn) v = *(const float4*)(hsrc + (size_t)nA * HH + k0);
        int kr = 16 + k0;
        As[(kr + 0) * 128 + lr] = v.x;
        As[(kr + 1) * 128 + lr] = v.y;
        As[(kr + 2) * 128 + lr] = v.z;
        As[(kr + 3) * 128 + lr] = v.w;
    }
    __syncthreads();

    unsigned long long accp[8][2];

    // ================= phase Z =================
    ACC_RESET();
    for (int chunk = 0; chunk < nch; ++chunk) {
        float* cur = Bs + (chunk & 1) * 2048;
        if (chunk + 1 < nch) ldB_zr(Bs + ((chunk + 1) & 1) * 2048, chunk + 1, 0, bk, bc);
        GEMM_CHUNK(As + chunk * 16 * 128, 128, cur);
        __syncthreads();
    }
#pragma unroll
    for (int i = 0; i < 8; ++i) {
        int ml = ty * 8 + i;
#pragma unroll
        for (int jp = 0; jp < 2; ++jp) {
            float2 v = unpack2(accp[i][jp]);
            int c = tx * 4 + 2 * jp;
            zs[ml * 128 + c]     = sigmoidf_(v.x + g_bzr[c]);
            zs[ml * 128 + c + 1] = sigmoidf_(v.y + g_bzr[c + 1]);
        }
    }

    // ================= phase R =================
    ACC_RESET();
    ldB_zr(Bs, 0, 128, bk, bc);
    __syncthreads();
    for (int chunk = 0; chunk < nch; ++chunk) {
        float* cur = Bs + (chunk & 1) * 2048;
        if (chunk + 1 < nch) ldB_zr(Bs + ((chunk + 1) & 1) * 2048, chunk + 1, 128, bk, bc);
        GEMM_CHUNK(As + chunk * 16 * 128, 128, cur);
        __syncthreads();
    }
#pragma unroll
    for (int i = 0; i < 8; ++i) {
        int ml = ty * 8 + i;
#pragma unroll
        for (int jp = 0; jp < 2; ++jp) {
            float2 v = unpack2(accp[i][jp]);
            int c = tx * 4 + 2 * jp;
            float r0 = sigmoidf_(v.x + g_bzr[128 + c]);
            float r1 = sigmoidf_(v.y + g_bzr[128 + c + 1]);
            float h0 = As[(16 + c) * 128 + ml];
            float h1 = As[(16 + c + 1) * 128 + ml];
            hrs[c * HRS + ml]       = h0 * r0;
            hrs[(c + 1) * HRS + ml] = h1 * r1;
        }
    }

    // ================= phase H =================
    ACC_RESET();
    ldB_h(Bs, 0, Wlh_bot, bk, bc);
    __syncthreads();
    for (int chunk = 0; chunk < nch; ++chunk) {
        float* cur = Bs + (chunk & 1) * 2048;
        if (chunk + 1 < nch) ldB_h(Bs + ((chunk + 1) & 1) * 2048, chunk + 1, Wlh_bot, bk, bc);
        if (chunk == 0) {
            GEMM_CHUNK(As, 128, cur);
        } else {
            GEMM_CHUNK(hrs + (chunk - 1) * 16 * HRS, HRS, cur);
        }
        __syncthreads();
    }

    // ================= combine =================
#pragma unroll
    for (int i = 0; i < 8; ++i) {
        int ml = ty * 8 + i;
        int n = n0 + ml;
        bool inb = (n < NN);
        bool wr = inb && (horizon ? true : (mk[n] != 0));
#pragma unroll
        for (int jp = 0; jp < 2; ++jp) {
            float2 v = unpack2(accp[i][jp]);
            int c = tx * 4 + 2 * jp;
#pragma unroll
            for (int u = 0; u < 2; ++u) {
                float val = (u == 0) ? v.x : v.y;
                int cc = c + u;
                float ht = tanhf(val + g_bh[cc]);
                float zv = zs[ml * 128 + cc];
                float heff = As[(16 + cc) * 128 + ml];
                float hn = zv * heff + (1.f - zv) * ht;
                if (horizon) {
                    if (inb) g_hw[(size_t)n * HH + cc] = hn;
                    hrs[ml * 129 + cc] = hn;           // reused for head pred
                } else {
                    if (wr) g_h[(size_t)n * HH + cc] = hn;
                    if (wrHw && inb) g_hw[(size_t)n * HH + cc] = wr ? hn : 0.f;
                }
            }
        }
    }

    // ================= fused head prediction (horizon only) =================
    if (horizon) {
        __syncthreads();                 // As reads in combine done before reuse
        if (tid < 96) {
            float4 w = *(const float4*)(headW + tid * 4);
            As[tid * 4 + 0] = w.x; As[tid * 4 + 1] = w.y;
            As[tid * 4 + 2] = w.z; As[tid * 4 + 3] = w.w;
        }
        __syncthreads();
        if (tid < 128) {
            int n = n0 + tid;
            if (n < NN) {
                float p0 = 0.f, p1 = 0.f, p2 = 0.f;
#pragma unroll 8
                for (int c = 0; c < 128; ++c) {
                    float hv = hrs[tid * 129 + c];
                    p0 += hv * As[c * 3 + 0];
                    p1 += hv * As[c * 3 + 1];
                    p2 += hv * As[c * 3 + 2];
                }
                p0 += headb[0]; p1 += headb[1]; p2 += headb[2];
                outk[n * 3 + 0] = p0;
                outk[n * 3 + 1] = p1;
                outk[n * 3 + 2] = p2;
                float di = g_dinv_all[11 * NN + n];
                float s = di * di;
                agghN[n * FF + 0] = s * p0;   // next horizon step's self-term
                agghN[n * FF + 1] = s * p1;
                agghN[n * FF + 2] = s * p2;
            }
        }
    }
}

// ---------------- transition / horizon helpers ----------------
__global__ void k_transition(const float* __restrict__ agg11) {
    int i = blockIdx.x * blockDim.x + threadIdx.x;
    if (i >= NN * FF) return;
    float v = agg11[i];
    g_aggh[i] = v;
    g_aggh[NN * FF + i] = v;
}

__global__ void k_scatter3(const int* __restrict__ ei11,
                           const float* __restrict__ pred,
                           float* __restrict__ target) {
    int e = blockIdx.x * blockDim.x + threadIdx.x;
    if (e >= EE) return;
    int s = ei11[e], d = ei11[EE + e];
    float nrm = g_nrm11[e];
    float p0 = pred[s * 3 + 0], p1 = pred[s * 3 + 1], p2 = pred[s * 3 + 2];
    float* o = target + (size_t)d * FF;
    REDV2(o, nrm * p0, nrm * p1);
    RED1(o + 2, nrm * p2);
}

// ---------------- launch ----------------
extern "C" void kernel_launch(void* const* d_in, const int* in_sizes, int n_in,
                              void* d_out, int out_size) {
    const float* x_seq = (const float*)d_in[0];
    const int*   ei    = (const int*)d_in[1];
    const float* ea    = (const float*)d_in[2];
    const unsigned char* mraw = (const unsigned char*)d_in[3];
    const float* Wcz = (const float*)d_in[4];
    const float* bcz = (const float*)d_in[5];
    const float* Wlz = (const float*)d_in[6];
    const float* blz = (const float*)d_in[7];
    const float* Wcr = (const float*)d_in[8];
    const float* bcr = (const float*)d_in[9];
    const float* Wlr = (const float*)d_in[10];
    const float* blr = (const float*)d_in[11];
    const float* Wch = (const float*)d_in[12];
    const float* bch = (const float*)d_in[13];
    const float* Wlh = (const float*)d_in[14];
    const float* blh = (const float*)d_in[15];
    const float* hW  = (const float*)d_in[16];
    const float* hb  = (const float*)d_in[17];
    float* out = (float*)d_out;

    void* p;
    cudaGetSymbolAddress(&p, g_agg_all);
    const float* agg_all = (const float*)p;
    cudaGetSymbolAddress(&p, g_aggh);
    float* aggh = (float*)p;

    static int s_init_done = 0;
    static cudaStream_t s2;
    static cudaEvent_t evFork;
    static cudaEvent_t evT[TT];
    if (!s_init_done) {
        cudaFuncSetAttribute(k_cell, cudaFuncAttributeMaxDynamicSharedMemorySize,
                             SMEM_CELL);
        cudaStreamCreateWithFlags(&s2, cudaStreamNonBlocking);
        cudaEventCreateWithFlags(&evFork, cudaEventDisableTiming);
        for (int t = 0; t < TT; ++t)
            cudaEventCreateWithFlags(&evT[t], cudaEventDisableTiming);
        s_init_done = 1;
    }

    const int THR = 256;
    const float* Wlh_bot = Wlh + 128 * 128;

    // ---- prologue (main stream) ----
    k_detect<<<1, THR>>>(mraw);
    k_convert<<<(NN + THR - 1) / THR, THR>>>(mraw);
    k_fuse<<<(6528 + 128 * 256 + THR - 1) / THR, THR>>>(Wcz, Wlz, blz, bcz,
                                                        Wcr, Wlr, blr, bcr,
                                                        Wch, Wlh, blh, bch);
    k_init<<<(NN * HH + THR - 1) / THR, THR>>>();
    k_deg_all<<<(TT * EE + THR - 1) / THR, THR>>>(ei, ea);
    k_dinv_fin<<<(TT * NN + THR - 1) / THR, THR>>>();
    k_aggself_all<<<(TT * NN + THR - 1) / THR, THR>>>(x_seq);
    k_scatter_one<<<(EE + THR - 1) / THR, THR>>>(ei, ea, x_seq, 0);

    // ---- fork: per-t scatters on s2, cells on main stream ----
    cudaEventRecord(evFork, 0);
    cudaStreamWaitEvent(s2, evFork, 0);
    for (int t = 1; t < TT; ++t) {
        k_scatter_one<<<(EE + THR - 1) / THR, THR, 0, s2>>>(ei, ea, x_seq, t);
        cudaEventRecord(evT[t], s2);
    }

    dim3 gC((NN + 127) / 128);

    for (int t = 0; t < TT; ++t) {
        if (t > 0) cudaStreamWaitEvent(0, evT[t], 0);   // join scatter t
        const float* aggt = agg_all + (size_t)t * NN * FF;
        int flags = (t == 11) ? 2 : 0;
        if (t == 0) flags |= 4;                         // h_eff == 0 (seen empty)
        k_cell<<<gC, THR_CELL, SMEM_CELL>>>(aggt, t, flags, Wlh_bot,
                                            hW, hb, nullptr, nullptr);
    }

    const float* agg11 = agg_all + (size_t)11 * NN * FF;
    k_transition<<<(NN * FF + THR - 1) / THR, THR>>>(agg11);

    const int* eiL = ei + (size_t)11 * 2 * EE;

    for (int k = 0; k < HOR; ++k) {
        const float* aggk = (k == 0) ? agg11 : (aggh + (size_t)(k & 1) * NN * FF);
        float* agghN = aggh + (size_t)((k + 1) & 1) * NN * FF;
        if (k > 0) {
            const float* predPrev = out + (size_t)(k - 1) * NN * OUTD;
            k_scatter3<<<(EE + THR - 1) / THR, THR>>>(
                eiL, predPrev, aggh + (size_t)(k & 1) * NN * FF);
        }
        k_cell<<<gC, THR_CELL, SMEM_CELL>>>(aggk, 11, 1, Wlh_bot, hW, hb,
                                            out + (size_t)k * NN * OUTD, agghN);
    }
}

// round 12
// speedup vs baseline: 2.0399x; 1.5738x over previous
#include <cuda_runtime.h>
#include <cuda_bf16.h>
#include <math.h>

#define NN 50000
#define EE 1600000
#define TT 12
#define FF 16
#define HH 128
#define OUTD 3
#define HOR 6

#define KTOT 144            // 128 (h) + 16 (agg)
#define ASTRIDE 152         // bf16 units per row (304 B) -> conflict-free ldmatrix
#define ROWB (ASTRIDE * 2)  // 304 bytes

// smem layout (bytes)
#define OFF_AHI 0
#define OFF_ALO 38912
#define OFF_BHI 77824
#define OFF_BLO 116736
#define OFF_HS  155648      // hs fp32 [128][129]
#define SMEM_CELL (155648 + 128 * 129 * 4)   // 221696

#define THR_CELL 512

// ---------------- scratch ----------------
__device__ float g_dinv_all[TT * NN];
__device__ float g_agg_all[(size_t)TT * NN * FF];
__device__ float g_aggh[2 * NN * FF];
__device__ float g_nrm11[EE];
__device__ float g_h[NN * HH];
__device__ float g_hw[NN * HH];
__device__ unsigned char g_maskc[TT * NN];
__device__ unsigned char g_meff[TT * NN];
__device__ float g_Bzr_top[16 * 256];
__device__ float g_bzr[256];
__device__ float g_Bzr_bot[128 * 256];
__device__ float g_Bh_top[16 * 128];
__device__ float g_bh[128];
__device__ int g_isbyte;
// bf16 weight splits, [n][ASTRIDE] row-major (k contiguous), per gate {z,r,h}
__device__ __align__(16) unsigned short g_Bsp_hi[3][128 * ASTRIDE];
__device__ __align__(16) unsigned short g_Bsp_lo[3][128 * ASTRIDE];

// ---------------- helpers ----------------
__device__ __forceinline__ unsigned int s2u(const void* p) {
    unsigned int a;
    asm("{ .reg .u64 t; cvta.to.shared.u64 t, %1; cvt.u32.u64 %0, t; }"
        : "=r"(a) : "l"(p));
    return a;
}
__device__ __forceinline__ float bfr(float x) {
    return __bfloat162float(__float2bfloat16_rn(x));
}
__device__ __forceinline__ unsigned int pkbf(float lo, float hi) {  // lo -> low half
    unsigned int r;
    asm("cvt.rn.bf16x2.f32 %0, %1, %2;" : "=r"(r) : "f"(hi), "f"(lo));
    return r;
}
__device__ __forceinline__ void ldm4(unsigned int* r, unsigned int addr) {
    asm volatile("ldmatrix.sync.aligned.m8n8.x4.shared.b16 {%0,%1,%2,%3}, [%4];"
        : "=r"(r[0]), "=r"(r[1]), "=r"(r[2]), "=r"(r[3]) : "r"(addr));
}
__device__ __forceinline__ void mma_bf(float* d, const unsigned int* a,
                                       const unsigned int* b) {
    asm volatile(
        "mma.sync.aligned.m16n8k16.row.col.f32.bf16.bf16.f32 "
        "{%0,%1,%2,%3}, {%4,%5,%6,%7}, {%8,%9}, {%0,%1,%2,%3};"
        : "+f"(d[0]), "+f"(d[1]), "+f"(d[2]), "+f"(d[3])
        : "r"(a[0]), "r"(a[1]), "r"(a[2]), "r"(a[3]), "r"(b[0]), "r"(b[1]));
}
__device__ __forceinline__ float sigmoidf_(float v) {
    return 1.0f / (1.0f + __expf(-v));
}

// ---------------- mask detection / conversion ----------------
__global__ void k_detect(const unsigned char* raw) {
    __shared__ int cnt;
    if (threadIdx.x == 0) cnt = 0;
    __syncthreads();
    int c = 0;
    for (int i = threadIdx.x; i < 4096; i += blockDim.x) c += (raw[i] != 0);
    atomicAdd(&cnt, c);
    __syncthreads();
    if (threadIdx.x == 0) g_isbyte = (cnt > 2048) ? 1 : 0;
}
__global__ void k_convert(const unsigned char* raw) {
    int n = blockIdx.x * blockDim.x + threadIdx.x;
    if (n >= NN) return;
    int isb = g_isbyte, seen = 0;
#pragma unroll
    for (int t = 0; t < TT; ++t) {
        int m = isb ? (raw[t * NN + n] != 0) : (((const int*)raw)[t * NN + n] != 0);
        g_maskc[t * NN + n] = (unsigned char)m;
        g_meff[t * NN + n] = (unsigned char)(m & seen);
        seen |= m;
    }
}

// ---------------- weight fusion ----------------
__global__ void k_fuse(const float* __restrict__ Wcz, const float* __restrict__ Wlz,
                       const float* __restrict__ blz, const float* __restrict__ bcz,
                       const float* __restrict__ Wcr, const float* __restrict__ Wlr,
                       const float* __restrict__ blr, const float* __restrict__ bcr,
                       const float* __restrict__ Wch, const float* __restrict__ Wlh,
                       const float* __restrict__ blh, const float* __restrict__ bch) {
    int i = blockIdx.x * blockDim.x + threadIdx.x;
    if (i < 16 * 256) {
        int k = i / 256, c = i % 256, cc = c & 127;
        const float* A = (c < 128) ? Wcz : Wcr;
        const float* B = (c < 128) ? Wlz : Wlr;
        float s = 0.f;
        for (int j = 0; j < 128; ++j) s += A[k * 128 + j] * B[j * 128 + cc];
        g_Bzr_top[i] = s;
    } else if (i < 4096 + 2048) {
        int r = i - 4096; int k = r / 128, c = r % 128;
        float s = 0.f;
        for (int j = 0; j < 128; ++j) s += Wch[k * 128 + j] * Wlh[j * 128 + c];
        g_Bh_top[r] = s;
    } else if (i < 6144 + 256) {
        int c = i - 6144; int cc = c & 127;
        const float* bc = (c < 128) ? bcz : bcr;
        const float* B  = (c < 128) ? Wlz : Wlr;
        const float* bl = (c < 128) ? blz : blr;
        float s = bl[cc];
        for (int j = 0; j < 128; ++j) s += bc[j] * B[j * 128 + cc];
        g_bzr[c] = s;
    } else if (i < 6400 + 128) {
        int c = i - 6400;
        float s = blh[c];
        for (int j = 0; j < 128; ++j) s += bch[j] * Wlh[j * 128 + c];
        g_bh[c] = s;
    } else if (i < 6528 + 128 * 256) {
        int r = i - 6528; int k = r / 256, c = r % 256;
        g_Bzr_bot[r] = (c < 128) ? Wlz[(128 + k) * 128 + c]
                                 : Wlr[(128 + k) * 128 + (c - 128)];
    }
}

// bf16 hi/lo splits: B[n][k] = W[k][n]; k 0..127 = bottom, 128..143 = top
__global__ void k_fuse2(const float* __restrict__ Wlh_bot) {
    int i = blockIdx.x * blockDim.x + threadIdx.x;
    if (i >= 3 * KTOT * 128) return;
    int g = i / (KTOT * 128), r = i - g * (KTOT * 128);
    int k = r / 128, n = r - k * 128;
    float w;
    if (k < 128) {
        if (g == 0)      w = g_Bzr_bot[k * 256 + n];
        else if (g == 1) w = g_Bzr_bot[k * 256 + 128 + n];
        else             w = Wlh_bot[k * 128 + n];
    } else {
        int kt = k - 128;
        if (g == 0)      w = g_Bzr_top[kt * 256 + n];
        else if (g == 1) w = g_Bzr_top[kt * 256 + 128 + n];
        else             w = g_Bh_top[kt * 128 + n];
    }
    float wh = bfr(w);
    g_Bsp_hi[g][n * ASTRIDE + k] = __bfloat16_as_ushort(__float2bfloat16_rn(wh));
    g_Bsp_lo[g][n * ASTRIDE + k] = __bfloat16_as_ushort(__float2bfloat16_rn(w - wh));
}

__global__ void k_init() {
    int i = blockIdx.x * blockDim.x + threadIdx.x;
    if (i < NN * HH) g_h[i] = 0.f;
    if (i < TT * NN) g_dinv_all[i] = 0.f;
}

// ---------------- degree / aggregation ----------------
__global__ void k_deg_all(const int* __restrict__ ei, const float* __restrict__ ea) {
    int e = blockIdx.x * blockDim.x + threadIdx.x;
    if (e >= TT * EE) return;
    int t = e / EE, le = e - t * EE;
    int dst = ei[(size_t)t * 2 * EE + EE + le];
    atomicAdd(&g_dinv_all[t * NN + dst], ea[(size_t)t * EE + le]);
}
__global__ void k_dinv_fin() {
    int i = blockIdx.x * blockDim.x + threadIdx.x;
    if (i < TT * NN) g_dinv_all[i] = rsqrtf(g_dinv_all[i] + 1.0f);
}
__global__ void k_aggself_all(const float* __restrict__ x_seq) {
    int i = blockIdx.x * blockDim.x + threadIdx.x;
    if (i >= TT * NN) return;
    int t = i / NN, n = i - t * NN;
    float di = g_dinv_all[i];
    float s = di * di;
    const float4* xp = (const float4*)(x_seq + (size_t)t * NN * FF + (size_t)n * FF);
    float4* op = (float4*)(g_agg_all + (size_t)t * NN * FF + (size_t)n * FF);
    float4 a = xp[0], b = xp[1], c = xp[2], d = xp[3];
    op[0] = make_float4(s * a.x, s * a.y, s * a.z, s * a.w);
    op[1] = make_float4(s * b.x, s * b.y, s * b.z, s * b.w);
    op[2] = make_float4(s * c.x, s * c.y, s * c.z, s * c.w);
    op[3] = make_float4(s * d.x, s * d.y, s * d.z, s * d.w);
}
#define REDV4(p, a, b, c, d)                                              \
    asm volatile("red.global.add.v4.f32 [%0], {%1,%2,%3,%4};"             \
                 :: "l"(p), "f"(a), "f"(b), "f"(c), "f"(d) : "memory")
#define REDV2(p, a, b)                                                    \
    asm volatile("red.global.add.v2.f32 [%0], {%1,%2};"                   \
                 :: "l"(p), "f"(a), "f"(b) : "memory")
#define RED1(p, a)                                                        \
    asm volatile("red.global.add.f32 [%0], %1;"                           \
                 :: "l"(p), "f"(a) : "memory")
__global__ void k_scatter_one(const int* __restrict__ ei, const float* __restrict__ ea,
                              const float* __restrict__ x_seq, int t) {
    int le = blockIdx.x * blockDim.x + threadIdx.x;
    if (le >= EE) return;
    const int* eit = ei + (size_t)t * 2 * EE;
    int s = eit[le], d = eit[EE + le];
    const float* dinv = g_dinv_all + t * NN;
    float nrm = dinv[s] * ea[(size_t)t * EE + le] * dinv[d];
    if (t == 11) g_nrm11[le] = nrm;
    const float4* xp = (const float4*)(x_seq + (size_t)t * NN * FF + (size_t)s * FF);
    float4 a = xp[0], b = xp[1], c = xp[2], dd = xp[3];
    float* o = g_agg_all + (size_t)t * NN * FF + (size_t)d * FF;
    REDV4(o + 0,  nrm * a.x,  nrm * a.y,  nrm * a.z,  nrm * a.w);
    REDV4(o + 4,  nrm * b.x,  nrm * b.y,  nrm * b.z,  nrm * b.w);
    REDV4(o + 8,  nrm * c.x,  nrm * c.y,  nrm * c.z,  nrm * c.w);
    REDV4(o + 12, nrm * dd.x, nrm * dd.y, nrm * dd.z, nrm * dd.w);
}

// ---------------- fused TGCN cell: mma.sync bf16 split GEMMs ----------------
// flags: bit0 = horizon, bit1 = write g_hw = mk ? hn : 0 (t==11), bit2 = h_eff==0
__global__ __launch_bounds__(THR_CELL, 1)
void k_cell(const float* __restrict__ agg, int t, int flags,
            const float* __restrict__ headW, const float* __restrict__ headb,
            float* __restrict__ outk, float* __restrict__ agghN) {
    extern __shared__ __align__(16) char smc[];
    char*  Ahi = smc + OFF_AHI;
    char*  Alo = smc + OFF_ALO;
    char*  Bhi = smc + OFF_BHI;
    char*  Blo = smc + OFF_BLO;
    float* hs  = (float*)(smc + OFF_HS);
    unsigned int sbase = s2u(smc);

    const int tid = threadIdx.x;
    const int nblk = blockIdx.x * 128;
    const bool horizon = (flags & 1) != 0;
    const bool wrHw = (flags & 2) != 0;
    const bool hz = (flags & 4) != 0;
    const float* hsrc = horizon ? g_hw : g_h;
    const unsigned char* me = g_meff + (size_t)t * NN;
    const unsigned char* mk = g_maskc + (size_t)t * NN;

    const int w = tid >> 5, l = tid & 31;
    const int m0 = (w & 3) * 32, n0 = (w >> 2) * 32;
    const int fg = l >> 2, fc = l & 3;      // fragment row group / col pair

    // ---- staging: A (h split + agg split), hs fp32, B gate-z ----
    {
        int row = tid >> 2, q = tid & 3;
        int nA = nblk + row;
        bool rowValid = nA < NN;
        bool rowOn = rowValid && (horizon || (me[nA] != 0));
        char* arow_h = Ahi + row * ROWB;
        char* arow_l = Alo + row * ROWB;
#pragma unroll
        for (int g8 = 0; g8 < 8; ++g8) {
            int k0 = q * 32 + g8 * 4;
            float4 v = make_float4(0.f, 0.f, 0.f, 0.f);
            if (rowOn) v = *(const float4*)(hsrc + (size_t)nA * HH + k0);
            hs[row * 129 + k0 + 0] = v.x;
            hs[row * 129 + k0 + 1] = v.y;
            hs[row * 129 + k0 + 2] = v.z;
            hs[row * 129 + k0 + 3] = v.w;
            float xh = bfr(v.x), yh = bfr(v.y), zh = bfr(v.z), wh = bfr(v.w);
            *(unsigned int*)(arow_h + k0 * 2)     = pkbf(xh, yh);
            *(unsigned int*)(arow_h + k0 * 2 + 4) = pkbf(zh, wh);
            *(unsigned int*)(arow_l + k0 * 2)     = pkbf(v.x - xh, v.y - yh);
            *(unsigned int*)(arow_l + k0 * 2 + 4) = pkbf(v.z - zh, v.w - wh);
        }
        {   // agg cols -> k 128..143
            float4 v = make_float4(0.f, 0.f, 0.f, 0.f);
            if (rowValid) v = *(const float4*)(agg + (size_t)nA * 16 + 4 * q);
            int kb = (128 + q * 4) * 2;
            float xh = bfr(v.x), yh = bfr(v.y), zh = bfr(v.z), wh = bfr(v.w);
            *(unsigned int*)(arow_h + kb)     = pkbf(xh, yh);
            *(unsigned int*)(arow_h + kb + 4) = pkbf(zh, wh);
            *(unsigned int*)(arow_l + kb)     = pkbf(v.x - xh, v.y - yh);
            *(unsigned int*)(arow_l + kb + 4) = pkbf(v.z - zh, v.w - wh);
        }
        const float4* sh = (const float4*)g_Bsp_hi[0];
        const float4* sl = (const float4*)g_Bsp_lo[0];
        float4* dh = (float4*)Bhi;
        float4* dl = (float4*)Blo;
        for (int i = tid; i < 128 * ASTRIDE / 8; i += THR_CELL) {
            dh[i] = sh[i]; dl[i] = sl[i];
        }
    }
    __syncthreads();

    // ldmatrix lane base addresses (k-offset added per tile)
    unsigned int aHiAd = sbase + OFF_AHI + (m0 + (l & 15)) * ROWB + (l >> 4) * 16;
    unsigned int aLoAd = aHiAd + (OFF_ALO - OFF_AHI);
    unsigned int bHiAd = sbase + OFF_BHI +
                         (n0 + (l >> 4) * 8 + (l & 7)) * ROWB + ((l >> 3) & 1) * 16;
    unsigned int bLoAd = bHiAd + (OFF_BLO - OFF_BHI);
    const int kt0 = hz ? 8 : 0;

    float dd[32];      // [am][bn][e] flattened: (am*4+bn)*4+e
    float zreg[32];

#define GATE_MMA()                                                          \
    _Pragma("unroll") for (int j = 0; j < 32; ++j) dd[j] = 0.f;             \
    for (int kt = kt0; kt < 9; ++kt) {                                      \
        unsigned int ah[2][4], al[2][4], bh[2][4], bl[2][4];                \
        ldm4(ah[0], aHiAd + kt * 32);                                       \
        ldm4(ah[1], aHiAd + kt * 32 + 16 * ROWB);                           \
        ldm4(al[0], aLoAd + kt * 32);                                       \
        ldm4(al[1], aLoAd + kt * 32 + 16 * ROWB);                           \
        ldm4(bh[0], bHiAd + kt * 32);                                       \
        ldm4(bh[1], bHiAd + kt * 32 + 16 * ROWB);                           \
        ldm4(bl[0], bLoAd + kt * 32);                                       \
        ldm4(bl[1], bLoAd + kt * 32 + 16 * ROWB);                           \
        _Pragma("unroll") for (int am = 0; am < 2; ++am)                    \
        _Pragma("unroll") for (int bn = 0; bn < 4; ++bn) {                  \
            float* dp = dd + (am * 4 + bn) * 4;                             \
            const unsigned int* bhp = &bh[bn >> 1][(bn & 1) * 2];           \
            const unsigned int* blp = &bl[bn >> 1][(bn & 1) * 2];           \
            mma_bf(dp, ah[am], bhp);                                        \
            mma_bf(dp, ah[am], blp);                                        \
            mma_bf(dp, al[am], bhp);                                        \
        }                                                                   \
    }

    // ================= gate Z =================
    GATE_MMA();
#pragma unroll
    for (int am = 0; am < 2; ++am)
#pragma unroll
    for (int bn = 0; bn < 4; ++bn)
#pragma unroll
    for (int e = 0; e < 4; ++e) {
        int idx = (am * 4 + bn) * 4 + e;
        int col = n0 + 8 * bn + 2 * fc + (e & 1);
        zreg[idx] = sigmoidf_(dd[idx] + g_bzr[col]);
    }
    __syncthreads();
    {   // stage B gate-r
        const float4* sh = (const float4*)g_Bsp_hi[1];
        const float4* sl = (const float4*)g_Bsp_lo[1];
        float4* dh = (float4*)Bhi;
        float4* dl = (float4*)Blo;
        for (int i = tid; i < 128 * ASTRIDE / 8; i += THR_CELL) {
            dh[i] = sh[i]; dl[i] = sl[i];
        }
    }
    __syncthreads();

    // ================= gate R =================
    GATE_MMA();
#pragma unroll
    for (int am = 0; am < 2; ++am)
#pragma unroll
    for (int bn = 0; bn < 4; ++bn)
#pragma unroll
    for (int eh = 0; eh < 2; ++eh) {
        int idx = (am * 4 + bn) * 4 + eh * 2;
        int row = m0 + 16 * am + fg + eh * 8;
        int cb = n0 + 8 * bn + 2 * fc;
        float r0 = sigmoidf_(dd[idx]     + g_bzr[128 + cb]);
        float r1 = sigmoidf_(dd[idx + 1] + g_bzr[128 + cb + 1]);
        if (!hz) {
            float p0 = hs[row * 129 + cb] * r0;
            float p1 = hs[row * 129 + cb + 1] * r1;
            float p0h = bfr(p0), p1h = bfr(p1);
            *(unsigned int*)(Ahi + row * ROWB + cb * 2) = pkbf(p0h, p1h);
            *(unsigned int*)(Alo + row * ROWB + cb * 2) = pkbf(p0 - p0h, p1 - p1h);
        }
    }
    __syncthreads();
    {   // stage B gate-h
        const float4* sh = (const float4*)g_Bsp_hi[2];
        const float4* sl = (const float4*)g_Bsp_lo[2];
        float4* dh = (float4*)Bhi;
        float4* dl = (float4*)Blo;
        for (int i = tid; i < 128 * ASTRIDE / 8; i += THR_CELL) {
            dh[i] = sh[i]; dl[i] = sl[i];
        }
    }
    __syncthreads();

    // ================= gate H + combine =================
    GATE_MMA();
#pragma unroll
    for (int am = 0; am < 2; ++am)
#pragma unroll
    for (int bn = 0; bn < 4; ++bn)
#pragma unroll
    for (int e = 0; e < 4; ++e) {
        int idx = (am * 4 + bn) * 4 + e;
        int row = m0 + 16 * am + fg + (e >> 1) * 8;
        int col = n0 + 8 * bn + 2 * fc + (e & 1);
        float ht = tanhf(dd[idx] + g_bh[col]);
        float z = zreg[idx];
        float h0 = hs[row * 129 + col];
        hs[row * 129 + col] = z * h0 + (1.f - z) * ht;
    }
    __syncthreads();

    if (horizon && tid < 96) {
        float4 wv = *(const float4*)(headW + tid * 4);
        ((float*)Bhi)[tid * 4 + 0] = wv.x; ((float*)Bhi)[tid * 4 + 1] = wv.y;
        ((float*)Bhi)[tid * 4 + 2] = wv.z; ((float*)Bhi)[tid * 4 + 3] = wv.w;
    }

    // ---- coalesced masked writeback ----
    {
        int row = tid >> 2, cg = (tid & 3) * 32;
        int n = nblk + row;
        if (n < NN) {
            bool wr = horizon ? true : (mk[n] != 0);
#pragma unroll
            for (int i4 = 0; i4 < 8; ++i4) {
                float4 v;
                v.x = hs[row * 129 + cg + 4 * i4 + 0];
                v.y = hs[row * 129 + cg + 4 * i4 + 1];
                v.z = hs[row * 129 + cg + 4 * i4 + 2];
                v.w = hs[row * 129 + cg + 4 * i4 + 3];
                if (horizon) {
                    *(float4*)(g_hw + (size_t)n * HH + cg + 4 * i4) = v;
                } else {
                    if (wr) *(float4*)(g_h + (size_t)n * HH + cg + 4 * i4) = v;
                    if (wrHw) {
                        float4 vz = wr ? v : make_float4(0.f, 0.f, 0.f, 0.f);
                        *(float4*)(g_hw + (size_t)n * HH + cg + 4 * i4) = vz;
                    }
                }
            }
        }
    }

    // ---- fused head prediction (horizon) ----
    if (horizon) {
        __syncthreads();
        if (tid < 128) {
            int n = nblk + tid;
            if (n < NN) {
                const float* hwv = (const float*)Bhi;
                float p0 = 0.f, p1 = 0.f, p2 = 0.f;
#pragma unroll 8
                for (int c = 0; c < 128; ++c) {
                    float hv = hs[tid * 129 + c];
                    p0 += hv * hwv[c * 3 + 0];
                    p1 += hv * hwv[c * 3 + 1];
                    p2 += hv * hwv[c * 3 + 2];
                }
                p0 += headb[0]; p1 += headb[1]; p2 += headb[2];
                outk[n * 3 + 0] = p0;
                outk[n * 3 + 1] = p1;
                outk[n * 3 + 2] = p2;
                float di = g_dinv_all[11 * NN + n];
                float s = di * di;
                agghN[n * FF + 0] = s * p0;
                agghN[n * FF + 1] = s * p1;
                agghN[n * FF + 2] = s * p2;
            }
        }
    }
}

// ---------------- transition / horizon helpers ----------------
__global__ void k_transition(const float* __restrict__ agg11) {
    int i = blockIdx.x * blockDim.x + threadIdx.x;
    if (i >= NN * FF) return;
    float v = agg11[i];
    g_aggh[i] = v;
    g_aggh[NN * FF + i] = v;
}
__global__ void k_scatter3(const int* __restrict__ ei11,
                           const float* __restrict__ pred,
                           float* __restrict__ target) {
    int e = blockIdx.x * blockDim.x + threadIdx.x;
    if (e >= EE) return;
    int s = ei11[e], d = ei11[EE + e];
    float nrm = g_nrm11[e];
    float p0 = pred[s * 3 + 0], p1 = pred[s * 3 + 1], p2 = pred[s * 3 + 2];
    float* o = target + (size_t)d * FF;
    REDV2(o, nrm * p0, nrm * p1);
    RED1(o + 2, nrm * p2);
}

// ---------------- launch ----------------
extern "C" void kernel_launch(void* const* d_in, const int* in_sizes, int n_in,
                              void* d_out, int out_size) {
    const float* x_seq = (const float*)d_in[0];
    const int*   ei    = (const int*)d_in[1];
    const float* ea    = (const float*)d_in[2];
    const unsigned char* mraw = (const unsigned char*)d_in[3];
    const float* Wcz = (const float*)d_in[4];
    const float* bcz = (const float*)d_in[5];
    const float* Wlz = (const float*)d_in[6];
    const float* blz = (const float*)d_in[7];
    const float* Wcr = (const float*)d_in[8];
    const float* bcr = (const float*)d_in[9];
    const float* Wlr = (const float*)d_in[10];
    const float* blr = (const float*)d_in[11];
    const float* Wch = (const float*)d_in[12];
    const float* bch = (const float*)d_in[13];
    const float* Wlh = (const float*)d_in[14];
    const float* blh = (const float*)d_in[15];
    const float* hW  = (const float*)d_in[16];
    const float* hb  = (const float*)d_in[17];
    float* out = (float*)d_out;

    void* p;
    cudaGetSymbolAddress(&p, g_agg_all);
    const float* agg_all = (const float*)p;
    cudaGetSymbolAddress(&p, g_aggh);
    float* aggh = (float*)p;

    static int s_init_done = 0;
    static cudaStream_t s2;
    static cudaEvent_t evFork;
    static cudaEvent_t evT[TT];
    if (!s_init_done) {
        cudaFuncSetAttribute(k_cell, cudaFuncAttributeMaxDynamicSharedMemorySize,
                             SMEM_CELL);
        cudaStreamCreateWithFlags(&s2, cudaStreamNonBlocking);
        cudaEventCreateWithFlags(&evFork, cudaEventDisableTiming);
        for (int t = 0; t < TT; ++t)
            cudaEventCreateWithFlags(&evT[t], cudaEventDisableTiming);
        s_init_done = 1;
    }

    const int THR = 256;
    const float* Wlh_bot = Wlh + 128 * 128;

    k_detect<<<1, THR>>>(mraw);
    k_convert<<<(NN + THR - 1) / THR, THR>>>(mraw);
    k_fuse<<<(6528 + 128 * 256 + THR - 1) / THR, THR>>>(Wcz, Wlz, blz, bcz,
                                                        Wcr, Wlr, blr, bcr,
                                                        Wch, Wlh, blh, bch);
    k_fuse2<<<(3 * KTOT * 128 + THR - 1) / THR, THR>>>(Wlh_bot);
    k_init<<<(NN * HH + THR - 1) / THR, THR>>>();
    k_deg_all<<<(TT * EE + THR - 1) / THR, THR>>>(ei, ea);
    k_dinv_fin<<<(TT * NN + THR - 1) / THR, THR>>>();
    k_aggself_all<<<(TT * NN + THR - 1) / THR, THR>>>(x_seq);
    k_scatter_one<<<(EE + THR - 1) / THR, THR>>>(ei, ea, x_seq, 0);

    cudaEventRecord(evFork, 0);
    cudaStreamWaitEvent(s2, evFork, 0);
    for (int t = 1; t < TT; ++t) {
        k_scatter_one<<<(EE + THR - 1) / THR, THR, 0, s2>>>(ei, ea, x_seq, t);
        cudaEventRecord(evT[t], s2);
    }

    dim3 gC((NN + 127) / 128);

    for (int t = 0; t < TT; ++t) {
        if (t > 0) cudaStreamWaitEvent(0, evT[t], 0);
        const float* aggt = agg_all + (size_t)t * NN * FF;
        int flags = (t == 11) ? 2 : 0;
        if (t == 0) flags |= 4;
        k_cell<<<gC, THR_CELL, SMEM_CELL>>>(aggt, t, flags, hW, hb,
                                            nullptr, nullptr);
    }

    const float* agg11 = agg_all + (size_t)11 * NN * FF;
    k_transition<<<(NN * FF + THR - 1) / THR, THR>>>(agg11);

    const int* eiL = ei + (size_t)11 * 2 * EE;

    for (int k = 0; k < HOR; ++k) {
        const float* aggk = (k == 0) ? agg11 : (aggh + (size_t)(k & 1) * NN * FF);
        float* agghN = aggh + (size_t)((k + 1) & 1) * NN * FF;
        if (k > 0) {
            const float* predPrev = out + (size_t)(k - 1) * NN * OUTD;
            k_scatter3<<<(EE + THR - 1) / THR, THR>>>(
                eiL, predPrev, aggh + (size_t)(k & 1) * NN * FF);
        }
        k_cell<<<gC, THR_CELL, SMEM_CELL>>>(aggk, 11, 1, hW, hb,
                                            out + (size_t)k * NN * OUTD, agghN);
    }
}